// round 9
// baseline (speedup 1.0000x reference)
#include <cuda_runtime.h>
#include <cuda_bf16.h>
#include <math.h>
#include <stdint.h>

#define BATCH 64
#define SEQ   1024
#define CDIM  128
#define M0    40.0f

// bf16 hi/lo scratch (zero-initialized device globals):
// Q,K row-major [b*n][c]; V transposed [b][c][n]
__device__ __align__(16) unsigned short g_Qh[BATCH * SEQ * CDIM];
__device__ __align__(16) unsigned short g_Ql[BATCH * SEQ * CDIM];
__device__ __align__(16) unsigned short g_Kh[BATCH * SEQ * CDIM];
__device__ __align__(16) unsigned short g_Kl[BATCH * SEQ * CDIM];
__device__ __align__(16) unsigned short g_Vth[BATCH * CDIM * SEQ];
__device__ __align__(16) unsigned short g_Vtl[BATCH * CDIM * SEQ];

// ---------------- helpers ----------------
static __device__ __forceinline__ uint32_t smem_u32(const void* p) {
    uint32_t a;
    asm("{ .reg .u64 t; cvta.to.shared.u64 t, %1; cvt.u32.u64 %0, t; }" : "=r"(a) : "l"(p));
    return a;
}
static __device__ __forceinline__ void ldmx4(uint32_t a, uint32_t* r) {
    asm volatile("ldmatrix.sync.aligned.m8n8.x4.shared.b16 {%0,%1,%2,%3}, [%4];"
                 : "=r"(r[0]), "=r"(r[1]), "=r"(r[2]), "=r"(r[3]) : "r"(a));
}
static __device__ __forceinline__ void mma16816(float* d, const uint32_t* a, const uint32_t* b) {
    asm volatile("mma.sync.aligned.m16n8k16.row.col.f32.bf16.bf16.f32 "
                 "{%0,%1,%2,%3}, {%4,%5,%6,%7}, {%8,%9}, {%0,%1,%2,%3};"
                 : "+f"(d[0]), "+f"(d[1]), "+f"(d[2]), "+f"(d[3])
                 : "r"(a[0]), "r"(a[1]), "r"(a[2]), "r"(a[3]), "r"(b[0]), "r"(b[1]));
}
// pack two floats -> bf16x2 (first arg -> low half)
static __device__ __forceinline__ uint32_t cvt2(float lo, float hi) {
    uint32_t r;
    asm("cvt.rn.bf16x2.f32 %0, %1, %2;" : "=r"(r) : "f"(hi), "f"(lo));
    return r;
}
static __device__ __forceinline__ float lo_f(uint32_t h) { return __uint_as_float(h << 16); }
static __device__ __forceinline__ float hi_f(uint32_t h) { return __uint_as_float(h & 0xffff0000u); }
#define CP16(d, s) asm volatile("cp.async.cg.shared.global [%0], [%1], 16;" :: "r"(d), "l"(s))
#define CP_COMMIT() asm volatile("cp.async.commit_group;" ::: "memory")

#define TS 272                    // stride: 256B-row tiles (Q/K/X/W)
#define VS 144                    // stride: 128B-row tiles (V^T stages)

// ---- attn smem: 3 rotating stage buffers (buf2 initially holds Q) ----
#define SSZ    71680              // stage: KH 17408 | KL 17408 | VH 18432 | VL 18432
#define S_KH   0
#define S_KL   17408
#define S_VH   34816
#define S_VL   53248
#define QH_OFF 0
#define QL_OFF 34816
#define ATT_SMEM (3 * SSZ)        // 215040

// ---- qkv smem layout ----
#define X_H    0
#define X_L    34816
#define W_H    69632
#define W_L    104448
#define QKV_SMEM 139264

// loaders (256 threads each)
static __device__ __forceinline__ void loadQ128(uint32_t sdst, const unsigned short* g, int tid) {
    #pragma unroll
    for (int i = 0; i < 8; i++) {
        int idx = tid + (i << 8);
        int r = idx >> 4, c = idx & 15;
        CP16(sdst + (uint32_t)r * TS + (uint32_t)c * 16, (const void*)(g + (size_t)r * CDIM + (c << 3)));
    }
}
static __device__ __forceinline__ void loadK64(uint32_t sdst, const unsigned short* g, int tid) {
    #pragma unroll
    for (int i = 0; i < 4; i++) {
        int idx = tid + (i << 8);
        int r = idx >> 4, c = idx & 15;
        CP16(sdst + (uint32_t)r * TS + (uint32_t)c * 16, (const void*)(g + (size_t)r * CDIM + (c << 3)));
    }
}
static __device__ __forceinline__ void loadV128x64(uint32_t sdst, const unsigned short* g, int tid) {
    #pragma unroll
    for (int i = 0; i < 4; i++) {
        int idx = tid + (i << 8);
        int r = idx >> 3, c = idx & 7;
        CP16(sdst + (uint32_t)r * VS + (uint32_t)c * 16, (const void*)(g + (size_t)r * SEQ + (c << 3)));
    }
}
static __device__ __forceinline__ void stage_load(uint32_t buf, size_t kbase, size_t vbase,
                                                  int kt, int tid) {
    loadK64(buf + S_KH, g_Kh + kbase + (size_t)kt * 64 * CDIM, tid);
    loadK64(buf + S_KL, g_Kl + kbase + (size_t)kt * 64 * CDIM, tid);
    loadV128x64(buf + S_VH, g_Vth + vbase + (size_t)kt * 64, tid);
    loadV128x64(buf + S_VL, g_Vtl + vbase + (size_t)kt * 64, tid);
}

// ============================================================================
// Kernel 1: QKV projection via mma.sync, 3-term bf16 split (round-6 version).
// ============================================================================
__global__ __launch_bounds__(256)
void qkv_mma(const float* __restrict__ x, const int* __restrict__ vls,
             const float* __restrict__ qw, const float* __restrict__ qb,
             const float* __restrict__ kw, const float* __restrict__ kb,
             const float* __restrict__ vw, const float* __restrict__ vb)
{
    extern __shared__ __align__(16) char sm[];
    const uint32_t sb = smem_u32(sm);
    const int tid = threadIdx.x, wid = tid >> 5, lane = tid & 31;
    const int row0 = blockIdx.x * 128;
    const int b = row0 >> 10, n0 = row0 & 1023;
    if (n0 >= vls[b]) return;

    const float4* xg = (const float4*)(x + (size_t)row0 * CDIM);
    #pragma unroll
    for (int i = 0; i < 16; i++) {
        int idx = tid + (i << 8);
        int r = idx >> 5, c4 = idx & 31;
        float4 v = xg[r * 32 + c4];
        uint32_t h0 = cvt2(v.x, v.y), h1 = cvt2(v.z, v.w);
        uint32_t l0 = cvt2(v.x - lo_f(h0), v.y - hi_f(h0));
        uint32_t l1 = cvt2(v.z - lo_f(h1), v.w - hi_f(h1));
        uint32_t ad = (uint32_t)r * TS + (uint32_t)c4 * 8;
        *(uint2*)(sm + X_H + ad) = make_uint2(h0, h1);
        *(uint2*)(sm + X_L + ad) = make_uint2(l0, l1);
    }

    const uint32_t qrow = (uint32_t)(wid * 16 + (lane & 15)) * TS + ((lane >> 4) & 1) * 16;
    const uint32_t brow = (uint32_t)(lane & 7) * TS + ((lane >> 3) & 1) * 16;
    const int r0l = wid * 16 + (lane >> 2);

    for (int w = 0; w < 3; w++) {
        const float* W  = (w == 0) ? qw : (w == 1) ? kw : vw;
        const float* Bs = (w == 0) ? qb : (w == 1) ? kb : vb;
        __syncthreads();
        const float4* wg = (const float4*)W;
        #pragma unroll
        for (int i = 0; i < 16; i++) {
            int idx = tid + (i << 8);
            int r = idx >> 5, c4 = idx & 31;
            float4 v = wg[r * 32 + c4];
            uint32_t h0 = cvt2(v.x, v.y), h1 = cvt2(v.z, v.w);
            uint32_t l0 = cvt2(v.x - lo_f(h0), v.y - hi_f(h0));
            uint32_t l1 = cvt2(v.z - lo_f(h1), v.w - hi_f(h1));
            uint32_t ad = (uint32_t)r * TS + (uint32_t)c4 * 8;
            *(uint2*)(sm + W_H + ad) = make_uint2(h0, h1);
            *(uint2*)(sm + W_L + ad) = make_uint2(l0, l1);
        }
        __syncthreads();

        const uint32_t Ah = sb + ((w < 2) ? X_H : W_H), Al = sb + ((w < 2) ? X_L : W_L);
        const uint32_t Bh = sb + ((w < 2) ? W_H : X_H), Bl = sb + ((w < 2) ? W_L : X_L);

        float acc[16][4];
        #pragma unroll
        for (int n = 0; n < 16; n++)
            #pragma unroll
            for (int q = 0; q < 4; q++) acc[n][q] = 0.f;

        #pragma unroll
        for (int ks = 0; ks < 8; ks++) {
            uint32_t ah[4], al[4];
            ldmx4(Ah + qrow + ks * 32, ah);
            ldmx4(Al + qrow + ks * 32, al);
            #pragma unroll
            for (int n = 0; n < 16; n++) {
                uint32_t bh[2], bl[2];
                uint32_t off = brow + (uint32_t)n * (8 * TS) + ks * 32;
                asm volatile("ldmatrix.sync.aligned.m8n8.x2.shared.b16 {%0,%1}, [%2];"
                             : "=r"(bh[0]), "=r"(bh[1]) : "r"(Bh + off));
                asm volatile("ldmatrix.sync.aligned.m8n8.x2.shared.b16 {%0,%1}, [%2];"
                             : "=r"(bl[0]), "=r"(bl[1]) : "r"(Bl + off));
                mma16816(acc[n], ah, bh);
                mma16816(acc[n], al, bh);
                mma16816(acc[n], ah, bl);
            }
        }

        if (w < 2) {
            unsigned short* Oh = (w == 0) ? g_Qh : g_Kh;
            unsigned short* Ol = (w == 0) ? g_Ql : g_Kl;
            size_t rA = (size_t)(row0 + r0l) * CDIM;
            size_t rB = (size_t)(row0 + r0l + 8) * CDIM;
            #pragma unroll
            for (int n = 0; n < 16; n++) {
                int c = n * 8 + (lane & 3) * 2;
                float b0 = __ldg(Bs + c), b1 = __ldg(Bs + c + 1);
                float v00 = acc[n][0] + b0, v01 = acc[n][1] + b1;
                float v10 = acc[n][2] + b0, v11 = acc[n][3] + b1;
                uint32_t hA = cvt2(v00, v01), hB = cvt2(v10, v11);
                *(uint32_t*)(Oh + rA + c) = hA;
                *(uint32_t*)(Oh + rB + c) = hB;
                *(uint32_t*)(Ol + rA + c) = cvt2(v00 - lo_f(hA), v01 - hi_f(hA));
                *(uint32_t*)(Ol + rB + c) = cvt2(v10 - lo_f(hB), v11 - hi_f(hB));
            }
        } else {
            float bc0 = __ldg(Bs + r0l), bc1 = __ldg(Bs + r0l + 8);
            size_t rA = (size_t)b * CDIM * SEQ + (size_t)r0l * SEQ + n0;
            size_t rB = rA + (size_t)8 * SEQ;
            #pragma unroll
            for (int n = 0; n < 16; n++) {
                int c = n * 8 + (lane & 3) * 2;
                float v00 = acc[n][0] + bc0, v01 = acc[n][1] + bc0;
                float v10 = acc[n][2] + bc1, v11 = acc[n][3] + bc1;
                uint32_t hA = cvt2(v00, v01), hB = cvt2(v10, v11);
                *(uint32_t*)(g_Vth + rA + c) = hA;
                *(uint32_t*)(g_Vth + rB + c) = hB;
                *(uint32_t*)(g_Vtl + rA + c) = cvt2(v00 - lo_f(hA), v01 - hi_f(hA));
                *(uint32_t*)(g_Vtl + rB + c) = cvt2(v10 - lo_f(hB), v11 - hi_f(hB));
            }
        }
    }
}

// ============================================================================
// Kernel 2: pipelined flash attention. Q frags in regs, triple-buffered
// stages, software-pipelined B-fragment loads, heavy-first CTA order.
// ============================================================================
__global__ __launch_bounds__(256)
void attn_mma(const int* __restrict__ vls, float* __restrict__ out)
{
    extern __shared__ __align__(16) char sm[];
    const uint32_t sb = smem_u32(sm);
    const int tid = threadIdx.x, wid = tid >> 5, lane = tid & 31;
    const int b = blockIdx.y;
    const int row0 = (gridDim.x - 1 - blockIdx.x) * 128;   // heavy tiles first
    const int vl = vls[b];
    float* og = out + ((size_t)b * SEQ + row0) * CDIM;

    if (row0 >= vl) {
        float4 z = make_float4(0.f, 0.f, 0.f, 0.f);
        float4* o4 = (float4*)og;
        for (int i = tid; i < 128 * 32; i += 256) o4[i] = z;
        return;
    }

    const uint32_t qrow = (uint32_t)(wid * 16 + (lane & 15)) * TS + ((lane >> 4) & 1) * 16;
    const uint32_t brwK = (uint32_t)((lane & 7) + ((lane >> 4) << 3)) * TS + ((lane >> 3) & 1) * 16;
    const uint32_t brwV = (uint32_t)((lane & 7) + ((lane >> 4) << 3)) * VS + ((lane >> 3) & 1) * 16;
    const int r0l = wid * 16 + (lane >> 2);
    const bool v0 = row0 + r0l < vl, v1 = row0 + r0l + 8 < vl;

    const size_t kbase = (size_t)b * SEQ * CDIM;
    const size_t vbase = (size_t)b * CDIM * SEQ;
    const int nst = (vl + 63) >> 6;
    const uint32_t buf0 = sb, buf1 = sb + SSZ, buf2 = sb + 2 * SSZ;

    loadQ128(buf2 + QH_OFF, g_Qh + kbase + (size_t)row0 * CDIM, tid);
    loadQ128(buf2 + QL_OFF, g_Ql + kbase + (size_t)row0 * CDIM, tid);
    CP_COMMIT();
    stage_load(buf0, kbase, vbase, 0, tid);
    CP_COMMIT();
    if (nst > 1) stage_load(buf1, kbase, vbase, 1, tid);
    CP_COMMIT();
    asm volatile("cp.async.wait_group 2;" ::: "memory");
    __syncthreads();

    uint32_t qh[8][4], ql[8][4];
    #pragma unroll
    for (int ks = 0; ks < 8; ks++) {
        ldmx4(buf2 + QH_OFF + qrow + ks * 32, qh[ks]);
        ldmx4(buf2 + QL_OFF + qrow + ks * 32, ql[ks]);
    }

    float oacc[16][4];
    #pragma unroll
    for (int n = 0; n < 16; n++)
        #pragma unroll
        for (int q = 0; q < 4; q++) oacc[n][q] = 0.f;
    float lsum0 = 0.f, lsum1 = 0.f;

    for (int t = 0; t < nst; t++) {
        asm volatile("cp.async.wait_group 1;" ::: "memory");
        __syncthreads();
        if (t + 2 < nst) {
            uint32_t pb = ((t + 2) % 3 == 0) ? buf0 : ((t + 2) % 3 == 1) ? buf1 : buf2;
            stage_load(pb, kbase, vbase, t + 2, tid);
        }
        CP_COMMIT();

        const uint32_t st = (t % 3 == 0) ? buf0 : (t % 3 == 1) ? buf1 : buf2;

        // ---- S = Q K^T (3 split terms, pipelined fragment loads) ----
        float sacc[8][4];
        #pragma unroll
        for (int n = 0; n < 8; n++)
            #pragma unroll
            for (int q = 0; q < 4; q++) sacc[n][q] = 0.f;

        {
            uint32_t bh[2][4], bl[2][4];
            ldmx4(st + S_KH + brwK, bh[0]);
            ldmx4(st + S_KL + brwK, bl[0]);
            #pragma unroll
            for (int ks = 0; ks < 8; ks++) {
                #pragma unroll
                for (int np = 0; np < 4; np++) {
                    const int cur = (ks * 4 + np) & 1, nxt = cur ^ 1;
                    if (!(ks == 7 && np == 3)) {
                        int nks = (np == 3) ? ks + 1 : ks;
                        int nnp = (np == 3) ? 0 : np + 1;
                        uint32_t off = brwK + (uint32_t)nnp * (16 * TS) + nks * 32;
                        ldmx4(st + S_KH + off, bh[nxt]);
                        ldmx4(st + S_KL + off, bl[nxt]);
                    }
                    mma16816(sacc[2 * np],     qh[ks], bh[cur]);
                    mma16816(sacc[2 * np + 1], qh[ks], bh[cur] + 2);
                    mma16816(sacc[2 * np],     ql[ks], bh[cur]);
                    mma16816(sacc[2 * np + 1], ql[ks], bh[cur] + 2);
                    mma16816(sacc[2 * np],     qh[ks], bl[cur]);
                    mma16816(sacc[2 * np + 1], qh[ks], bl[cur] + 2);
                }
            }
        }

        // ---- softmax (fixed M0; masked lanes -> 0) ----
        const int cb = t * 64;
        #pragma unroll
        for (int n = 0; n < 8; n++) {
            int c0 = cb + n * 8 + (lane & 3) * 2;
            float e0 = (v0 && c0 < vl)     ? __expf(sacc[n][0] - M0) : 0.f;
            float e1 = (v0 && c0 + 1 < vl) ? __expf(sacc[n][1] - M0) : 0.f;
            float e2 = (v1 && c0 < vl)     ? __expf(sacc[n][2] - M0) : 0.f;
            float e3 = (v1 && c0 + 1 < vl) ? __expf(sacc[n][3] - M0) : 0.f;
            lsum0 += e0 + e1;
            lsum1 += e2 + e3;
            sacc[n][0] = e0; sacc[n][1] = e1; sacc[n][2] = e2; sacc[n][3] = e3;
        }

        // ---- O += P V (3 split terms, pipelined fragment loads) ----
        {
            uint32_t bh[2][4], bl[2][4];
            ldmx4(st + S_VH + brwV, bh[0]);
            ldmx4(st + S_VL + brwV, bl[0]);
            #pragma unroll
            for (int ks = 0; ks < 4; ks++) {
                const float* t0 = sacc[2 * ks];
                const float* t1 = sacc[2 * ks + 1];
                uint32_t pfh[4], pfl[4];
                pfh[0] = cvt2(t0[0], t0[1]);
                pfh[1] = cvt2(t0[2], t0[3]);
                pfh[2] = cvt2(t1[0], t1[1]);
                pfh[3] = cvt2(t1[2], t1[3]);
                pfl[0] = cvt2(t0[0] - lo_f(pfh[0]), t0[1] - hi_f(pfh[0]));
                pfl[1] = cvt2(t0[2] - lo_f(pfh[1]), t0[3] - hi_f(pfh[1]));
                pfl[2] = cvt2(t1[0] - lo_f(pfh[2]), t1[1] - hi_f(pfh[2]));
                pfl[3] = cvt2(t1[2] - lo_f(pfh[3]), t1[3] - hi_f(pfh[3]));
                #pragma unroll
                for (int np = 0; np < 8; np++) {
                    const int cur = (ks * 8 + np) & 1, nxt = cur ^ 1;
                    if (!(ks == 3 && np == 7)) {
                        int nks = (np == 7) ? ks + 1 : ks;
                        int nnp = (np == 7) ? 0 : np + 1;
                        uint32_t off = brwV + (uint32_t)nnp * (16 * VS) + nks * 32;
                        ldmx4(st + S_VH + off, bh[nxt]);
                        ldmx4(st + S_VL + off, bl[nxt]);
                    }
                    mma16816(oacc[2 * np],     pfh, bh[cur]);
                    mma16816(oacc[2 * np + 1], pfh, bh[cur] + 2);
                    mma16816(oacc[2 * np],     pfl, bh[cur]);
                    mma16816(oacc[2 * np + 1], pfl, bh[cur] + 2);
                    mma16816(oacc[2 * np],     pfh, bl[cur]);
                    mma16816(oacc[2 * np + 1], pfh, bl[cur] + 2);
                }
            }
        }
    }

    // ---- epilogue ----
    lsum0 += __shfl_xor_sync(0xffffffffu, lsum0, 1);
    lsum0 += __shfl_xor_sync(0xffffffffu, lsum0, 2);
    lsum1 += __shfl_xor_sync(0xffffffffu, lsum1, 1);
    lsum1 += __shfl_xor_sync(0xffffffffu, lsum1, 2);
    float inv0 = v0 ? (1.f / lsum0) : 0.f;
    float inv1 = v1 ? (1.f / lsum1) : 0.f;

    #pragma unroll
    for (int n = 0; n < 16; n++) {
        int c = n * 8 + (lane & 3) * 2;
        float2* p0 = (float2*)(og + (size_t)r0l * CDIM + c);
        float2* p1 = (float2*)(og + (size_t)(r0l + 8) * CDIM + c);
        *p0 = make_float2(oacc[n][0] * inv0, oacc[n][1] * inv0);
        *p1 = make_float2(oacc[n][2] * inv1, oacc[n][3] * inv1);
    }
}

// ============================================================================
extern "C" void kernel_launch(void* const* d_in, const int* in_sizes, int n_in,
                              void* d_out, int out_size)
{
    const float* x  = (const float*)d_in[0];
    const int*   vl = (const int*)  d_in[1];
    const float* qw = (const float*)d_in[2];
    const float* qb = (const float*)d_in[3];
    const float* kw = (const float*)d_in[4];
    const float* kb = (const float*)d_in[5];
    const float* vw = (const float*)d_in[6];
    const float* vb = (const float*)d_in[7];
    float* out = (float*)d_out;

    cudaFuncSetAttribute(qkv_mma,  cudaFuncAttributeMaxDynamicSharedMemorySize, QKV_SMEM);
    cudaFuncSetAttribute(attn_mma, cudaFuncAttributeMaxDynamicSharedMemorySize, ATT_SMEM);

    qkv_mma<<<(BATCH * SEQ) / 128, 256, QKV_SMEM>>>(x, vl, qw, qb, kw, kb, vw, vb);
    dim3 grid(SEQ / 128, BATCH);
    attn_mma<<<grid, 256, ATT_SMEM>>>(vl, out);
}

// round 10
// speedup vs baseline: 1.0061x; 1.0061x over previous
#include <cuda_runtime.h>
#include <cuda_bf16.h>
#include <math.h>
#include <stdint.h>

#define BATCH 64
#define SEQ   1024
#define CDIM  128
#define M0    40.0f

// bf16 hi/lo scratch (zero-initialized device globals):
// Q,K row-major [b*n][c]; V transposed [b][c][n]
__device__ __align__(16) unsigned short g_Qh[BATCH * SEQ * CDIM];
__device__ __align__(16) unsigned short g_Ql[BATCH * SEQ * CDIM];
__device__ __align__(16) unsigned short g_Kh[BATCH * SEQ * CDIM];
__device__ __align__(16) unsigned short g_Kl[BATCH * SEQ * CDIM];
__device__ __align__(16) unsigned short g_Vth[BATCH * CDIM * SEQ];
__device__ __align__(16) unsigned short g_Vtl[BATCH * CDIM * SEQ];

// ---------------- helpers ----------------
static __device__ __forceinline__ uint32_t smem_u32(const void* p) {
    uint32_t a;
    asm("{ .reg .u64 t; cvta.to.shared.u64 t, %1; cvt.u32.u64 %0, t; }" : "=r"(a) : "l"(p));
    return a;
}
static __device__ __forceinline__ void ldmx4(uint32_t a, uint32_t* r) {
    asm volatile("ldmatrix.sync.aligned.m8n8.x4.shared.b16 {%0,%1,%2,%3}, [%4];"
                 : "=r"(r[0]), "=r"(r[1]), "=r"(r[2]), "=r"(r[3]) : "r"(a));
}
static __device__ __forceinline__ void mma16816(float* d, const uint32_t* a, const uint32_t* b) {
    asm volatile("mma.sync.aligned.m16n8k16.row.col.f32.bf16.bf16.f32 "
                 "{%0,%1,%2,%3}, {%4,%5,%6,%7}, {%8,%9}, {%0,%1,%2,%3};"
                 : "+f"(d[0]), "+f"(d[1]), "+f"(d[2]), "+f"(d[3])
                 : "r"(a[0]), "r"(a[1]), "r"(a[2]), "r"(a[3]), "r"(b[0]), "r"(b[1]));
}
// pack two floats -> bf16x2 (first arg -> low half)
static __device__ __forceinline__ uint32_t cvt2(float lo, float hi) {
    uint32_t r;
    asm("cvt.rn.bf16x2.f32 %0, %1, %2;" : "=r"(r) : "f"(hi), "f"(lo));
    return r;
}
static __device__ __forceinline__ float lo_f(uint32_t h) { return __uint_as_float(h << 16); }
static __device__ __forceinline__ float hi_f(uint32_t h) { return __uint_as_float(h & 0xffff0000u); }
#define CP16(d, s) asm volatile("cp.async.cg.shared.global [%0], [%1], 16;" :: "r"(d), "l"(s))
#define CP_COMMIT() asm volatile("cp.async.commit_group;" ::: "memory")

#define TS 272                    // stride: 256B-row tiles (Q/K/X/W)
#define VS 144                    // stride: 128B-row tiles (V^T stages)

// ---- attn smem: 3 rotating stage buffers (buf2 initially holds Q) ----
#define SSZ    71680              // stage: KH 17408 | KL 17408 | VH 18432 | VL 18432
#define S_KH   0
#define S_KL   17408
#define S_VH   34816
#define S_VL   53248
#define QH_OFF 0
#define QL_OFF 34816
#define ATT_SMEM (3 * SSZ)        // 215040

// ---- qkv smem layout ----
#define X_H    0
#define X_L    34816
#define W_H    69632
#define W_L    104448
#define QKV_SMEM 139264

// loaders (256 threads each)
static __device__ __forceinline__ void loadQ128(uint32_t sdst, const unsigned short* g, int tid) {
    #pragma unroll
    for (int i = 0; i < 8; i++) {
        int idx = tid + (i << 8);
        int r = idx >> 4, c = idx & 15;
        CP16(sdst + (uint32_t)r * TS + (uint32_t)c * 16, (const void*)(g + (size_t)r * CDIM + (c << 3)));
    }
}
static __device__ __forceinline__ void loadK64(uint32_t sdst, const unsigned short* g, int tid) {
    #pragma unroll
    for (int i = 0; i < 4; i++) {
        int idx = tid + (i << 8);
        int r = idx >> 4, c = idx & 15;
        CP16(sdst + (uint32_t)r * TS + (uint32_t)c * 16, (const void*)(g + (size_t)r * CDIM + (c << 3)));
    }
}
static __device__ __forceinline__ void loadV128x64(uint32_t sdst, const unsigned short* g, int tid) {
    #pragma unroll
    for (int i = 0; i < 4; i++) {
        int idx = tid + (i << 8);
        int r = idx >> 3, c = idx & 7;
        CP16(sdst + (uint32_t)r * VS + (uint32_t)c * 16, (const void*)(g + (size_t)r * SEQ + (c << 3)));
    }
}
static __device__ __forceinline__ void stage_load(uint32_t buf, size_t kbase, size_t vbase,
                                                  int kt, int tid) {
    loadK64(buf + S_KH, g_Kh + kbase + (size_t)kt * 64 * CDIM, tid);
    loadK64(buf + S_KL, g_Kl + kbase + (size_t)kt * 64 * CDIM, tid);
    loadV128x64(buf + S_VH, g_Vth + vbase + (size_t)kt * 64, tid);
    loadV128x64(buf + S_VL, g_Vtl + vbase + (size_t)kt * 64, tid);
}

// ============================================================================
// Kernel 1: QKV projection via mma.sync, 3-term bf16 split (round-6 version).
// ============================================================================
__global__ __launch_bounds__(256)
void qkv_mma(const float* __restrict__ x, const int* __restrict__ vls,
             const float* __restrict__ qw, const float* __restrict__ qb,
             const float* __restrict__ kw, const float* __restrict__ kb,
             const float* __restrict__ vw, const float* __restrict__ vb)
{
    extern __shared__ __align__(16) char sm[];
    const uint32_t sb = smem_u32(sm);
    const int tid = threadIdx.x, wid = tid >> 5, lane = tid & 31;
    const int row0 = blockIdx.x * 128;
    const int b = row0 >> 10, n0 = row0 & 1023;
    if (n0 >= vls[b]) return;

    const float4* xg = (const float4*)(x + (size_t)row0 * CDIM);
    #pragma unroll
    for (int i = 0; i < 16; i++) {
        int idx = tid + (i << 8);
        int r = idx >> 5, c4 = idx & 31;
        float4 v = xg[r * 32 + c4];
        uint32_t h0 = cvt2(v.x, v.y), h1 = cvt2(v.z, v.w);
        uint32_t l0 = cvt2(v.x - lo_f(h0), v.y - hi_f(h0));
        uint32_t l1 = cvt2(v.z - lo_f(h1), v.w - hi_f(h1));
        uint32_t ad = (uint32_t)r * TS + (uint32_t)c4 * 8;
        *(uint2*)(sm + X_H + ad) = make_uint2(h0, h1);
        *(uint2*)(sm + X_L + ad) = make_uint2(l0, l1);
    }

    const uint32_t qrow = (uint32_t)(wid * 16 + (lane & 15)) * TS + ((lane >> 4) & 1) * 16;
    const uint32_t brow = (uint32_t)(lane & 7) * TS + ((lane >> 3) & 1) * 16;
    const int r0l = wid * 16 + (lane >> 2);

    for (int w = 0; w < 3; w++) {
        const float* W  = (w == 0) ? qw : (w == 1) ? kw : vw;
        const float* Bs = (w == 0) ? qb : (w == 1) ? kb : vb;
        __syncthreads();
        const float4* wg = (const float4*)W;
        #pragma unroll
        for (int i = 0; i < 16; i++) {
            int idx = tid + (i << 8);
            int r = idx >> 5, c4 = idx & 31;
            float4 v = wg[r * 32 + c4];
            uint32_t h0 = cvt2(v.x, v.y), h1 = cvt2(v.z, v.w);
            uint32_t l0 = cvt2(v.x - lo_f(h0), v.y - hi_f(h0));
            uint32_t l1 = cvt2(v.z - lo_f(h1), v.w - hi_f(h1));
            uint32_t ad = (uint32_t)r * TS + (uint32_t)c4 * 8;
            *(uint2*)(sm + W_H + ad) = make_uint2(h0, h1);
            *(uint2*)(sm + W_L + ad) = make_uint2(l0, l1);
        }
        __syncthreads();

        const uint32_t Ah = sb + ((w < 2) ? X_H : W_H), Al = sb + ((w < 2) ? X_L : W_L);
        const uint32_t Bh = sb + ((w < 2) ? W_H : X_H), Bl = sb + ((w < 2) ? W_L : X_L);

        float acc[16][4];
        #pragma unroll
        for (int n = 0; n < 16; n++)
            #pragma unroll
            for (int q = 0; q < 4; q++) acc[n][q] = 0.f;

        #pragma unroll
        for (int ks = 0; ks < 8; ks++) {
            uint32_t ah[4], al[4];
            ldmx4(Ah + qrow + ks * 32, ah);
            ldmx4(Al + qrow + ks * 32, al);
            #pragma unroll
            for (int n = 0; n < 16; n++) {
                uint32_t bh[2], bl[2];
                uint32_t off = brow + (uint32_t)n * (8 * TS) + ks * 32;
                asm volatile("ldmatrix.sync.aligned.m8n8.x2.shared.b16 {%0,%1}, [%2];"
                             : "=r"(bh[0]), "=r"(bh[1]) : "r"(Bh + off));
                asm volatile("ldmatrix.sync.aligned.m8n8.x2.shared.b16 {%0,%1}, [%2];"
                             : "=r"(bl[0]), "=r"(bl[1]) : "r"(Bl + off));
                mma16816(acc[n], ah, bh);
                mma16816(acc[n], al, bh);
                mma16816(acc[n], ah, bl);
            }
        }

        if (w < 2) {
            unsigned short* Oh = (w == 0) ? g_Qh : g_Kh;
            unsigned short* Ol = (w == 0) ? g_Ql : g_Kl;
            size_t rA = (size_t)(row0 + r0l) * CDIM;
            size_t rB = (size_t)(row0 + r0l + 8) * CDIM;
            #pragma unroll
            for (int n = 0; n < 16; n++) {
                int c = n * 8 + (lane & 3) * 2;
                float b0 = __ldg(Bs + c), b1 = __ldg(Bs + c + 1);
                float v00 = acc[n][0] + b0, v01 = acc[n][1] + b1;
                float v10 = acc[n][2] + b0, v11 = acc[n][3] + b1;
                uint32_t hA = cvt2(v00, v01), hB = cvt2(v10, v11);
                *(uint32_t*)(Oh + rA + c) = hA;
                *(uint32_t*)(Oh + rB + c) = hB;
                *(uint32_t*)(Ol + rA + c) = cvt2(v00 - lo_f(hA), v01 - hi_f(hA));
                *(uint32_t*)(Ol + rB + c) = cvt2(v10 - lo_f(hB), v11 - hi_f(hB));
            }
        } else {
            float bc0 = __ldg(Bs + r0l), bc1 = __ldg(Bs + r0l + 8);
            size_t rA = (size_t)b * CDIM * SEQ + (size_t)r0l * SEQ + n0;
            size_t rB = rA + (size_t)8 * SEQ;
            #pragma unroll
            for (int n = 0; n < 16; n++) {
                int c = n * 8 + (lane & 3) * 2;
                float v00 = acc[n][0] + bc0, v01 = acc[n][1] + bc0;
                float v10 = acc[n][2] + bc1, v11 = acc[n][3] + bc1;
                uint32_t hA = cvt2(v00, v01), hB = cvt2(v10, v11);
                *(uint32_t*)(g_Vth + rA + c) = hA;
                *(uint32_t*)(g_Vth + rB + c) = hB;
                *(uint32_t*)(g_Vtl + rA + c) = cvt2(v00 - lo_f(hA), v01 - hi_f(hA));
                *(uint32_t*)(g_Vtl + rB + c) = cvt2(v10 - lo_f(hB), v11 - hi_f(hB));
            }
        }
    }
}

// ============================================================================
// Kernel 2: pipelined flash attention. Q frags in regs, triple-buffered
// stages, distance-4 accumulator interleave (term-major over n-pair groups).
// ============================================================================
__global__ __launch_bounds__(256)
void attn_mma(const int* __restrict__ vls, float* __restrict__ out)
{
    extern __shared__ __align__(16) char sm[];
    const uint32_t sb = smem_u32(sm);
    const int tid = threadIdx.x, wid = tid >> 5, lane = tid & 31;
    const int b = blockIdx.y;
    const int row0 = (gridDim.x - 1 - blockIdx.x) * 128;   // heavy tiles first
    const int vl = vls[b];
    float* og = out + ((size_t)b * SEQ + row0) * CDIM;

    if (row0 >= vl) {
        float4 z = make_float4(0.f, 0.f, 0.f, 0.f);
        float4* o4 = (float4*)og;
        for (int i = tid; i < 128 * 32; i += 256) o4[i] = z;
        return;
    }

    const uint32_t qrow = (uint32_t)(wid * 16 + (lane & 15)) * TS + ((lane >> 4) & 1) * 16;
    const uint32_t brwK = (uint32_t)((lane & 7) + ((lane >> 4) << 3)) * TS + ((lane >> 3) & 1) * 16;
    const uint32_t brwV = (uint32_t)((lane & 7) + ((lane >> 4) << 3)) * VS + ((lane >> 3) & 1) * 16;
    const int r0l = wid * 16 + (lane >> 2);
    const bool v0 = row0 + r0l < vl, v1 = row0 + r0l + 8 < vl;

    const size_t kbase = (size_t)b * SEQ * CDIM;
    const size_t vbase = (size_t)b * CDIM * SEQ;
    const int nst = (vl + 63) >> 6;
    const uint32_t buf0 = sb, buf1 = sb + SSZ, buf2 = sb + 2 * SSZ;

    loadQ128(buf2 + QH_OFF, g_Qh + kbase + (size_t)row0 * CDIM, tid);
    loadQ128(buf2 + QL_OFF, g_Ql + kbase + (size_t)row0 * CDIM, tid);
    CP_COMMIT();
    stage_load(buf0, kbase, vbase, 0, tid);
    CP_COMMIT();
    if (nst > 1) stage_load(buf1, kbase, vbase, 1, tid);
    CP_COMMIT();
    asm volatile("cp.async.wait_group 2;" ::: "memory");
    __syncthreads();

    uint32_t qh[8][4], ql[8][4];
    #pragma unroll
    for (int ks = 0; ks < 8; ks++) {
        ldmx4(buf2 + QH_OFF + qrow + ks * 32, qh[ks]);
        ldmx4(buf2 + QL_OFF + qrow + ks * 32, ql[ks]);
    }

    float oacc[16][4];
    #pragma unroll
    for (int n = 0; n < 16; n++)
        #pragma unroll
        for (int q = 0; q < 4; q++) oacc[n][q] = 0.f;
    float lsum0 = 0.f, lsum1 = 0.f;

    for (int t = 0; t < nst; t++) {
        asm volatile("cp.async.wait_group 1;" ::: "memory");
        __syncthreads();                       // cp.async visibility + buffer-free
        if (t + 2 < nst) {
            uint32_t pb = ((t + 2) % 3 == 0) ? buf0 : ((t + 2) % 3 == 1) ? buf1 : buf2;
            stage_load(pb, kbase, vbase, t + 2, tid);
        }
        CP_COMMIT();

        const uint32_t st = (t % 3 == 0) ? buf0 : (t % 3 == 1) ? buf1 : buf2;

        // ---- S = Q K^T: groups of n-pairs, term-major, acc distance 4 ----
        float sacc[8][4];
        #pragma unroll
        for (int n = 0; n < 8; n++)
            #pragma unroll
            for (int q = 0; q < 4; q++) sacc[n][q] = 0.f;

        #pragma unroll
        for (int ks = 0; ks < 8; ks++) {
            #pragma unroll
            for (int g = 0; g < 2; g++) {
                uint32_t b0h[4], b0l[4], b1h[4], b1l[4];
                uint32_t off0 = brwK + (uint32_t)(2 * g)     * (16 * TS) + ks * 32;
                uint32_t off1 = brwK + (uint32_t)(2 * g + 1) * (16 * TS) + ks * 32;
                ldmx4(st + S_KH + off0, b0h);
                ldmx4(st + S_KL + off0, b0l);
                ldmx4(st + S_KH + off1, b1h);
                ldmx4(st + S_KL + off1, b1l);
                float* a0 = sacc[4 * g + 0];
                float* a1 = sacc[4 * g + 1];
                float* a2 = sacc[4 * g + 2];
                float* a3 = sacc[4 * g + 3];
                mma16816(a0, qh[ks], b0h);  mma16816(a1, qh[ks], b0h + 2);
                mma16816(a2, qh[ks], b1h);  mma16816(a3, qh[ks], b1h + 2);
                mma16816(a0, ql[ks], b0h);  mma16816(a1, ql[ks], b0h + 2);
                mma16816(a2, ql[ks], b1h);  mma16816(a3, ql[ks], b1h + 2);
                mma16816(a0, qh[ks], b0l);  mma16816(a1, qh[ks], b0l + 2);
                mma16816(a2, qh[ks], b1l);  mma16816(a3, qh[ks], b1l + 2);
            }
        }

        // ---- softmax (fixed M0; masked lanes -> 0) ----
        const int cb = t * 64;
        #pragma unroll
        for (int n = 0; n < 8; n++) {
            int c0 = cb + n * 8 + (lane & 3) * 2;
            float e0 = (v0 && c0 < vl)     ? __expf(sacc[n][0] - M0) : 0.f;
            float e1 = (v0 && c0 + 1 < vl) ? __expf(sacc[n][1] - M0) : 0.f;
            float e2 = (v1 && c0 < vl)     ? __expf(sacc[n][2] - M0) : 0.f;
            float e3 = (v1 && c0 + 1 < vl) ? __expf(sacc[n][3] - M0) : 0.f;
            lsum0 += e0 + e1;
            lsum1 += e2 + e3;
            sacc[n][0] = e0; sacc[n][1] = e1; sacc[n][2] = e2; sacc[n][3] = e3;
        }

        // ---- O += P V: groups of n-pairs, term-major, acc distance 4 ----
        #pragma unroll
        for (int ks = 0; ks < 4; ks++) {
            const float* t0 = sacc[2 * ks];
            const float* t1 = sacc[2 * ks + 1];
            uint32_t pfh[4], pfl[4];
            pfh[0] = cvt2(t0[0], t0[1]);
            pfh[1] = cvt2(t0[2], t0[3]);
            pfh[2] = cvt2(t1[0], t1[1]);
            pfh[3] = cvt2(t1[2], t1[3]);
            pfl[0] = cvt2(t0[0] - lo_f(pfh[0]), t0[1] - hi_f(pfh[0]));
            pfl[1] = cvt2(t0[2] - lo_f(pfh[1]), t0[3] - hi_f(pfh[1]));
            pfl[2] = cvt2(t1[0] - lo_f(pfh[2]), t1[1] - hi_f(pfh[2]));
            pfl[3] = cvt2(t1[2] - lo_f(pfh[3]), t1[3] - hi_f(pfh[3]));
            #pragma unroll
            for (int g = 0; g < 4; g++) {
                uint32_t b0h[4], b0l[4], b1h[4], b1l[4];
                uint32_t off0 = brwV + (uint32_t)(2 * g)     * (16 * VS) + ks * 32;
                uint32_t off1 = brwV + (uint32_t)(2 * g + 1) * (16 * VS) + ks * 32;
                ldmx4(st + S_VH + off0, b0h);
                ldmx4(st + S_VL + off0, b0l);
                ldmx4(st + S_VH + off1, b1h);
                ldmx4(st + S_VL + off1, b1l);
                float* o0 = oacc[4 * g + 0];
                float* o1 = oacc[4 * g + 1];
                float* o2 = oacc[4 * g + 2];
                float* o3 = oacc[4 * g + 3];
                mma16816(o0, pfh, b0h);  mma16816(o1, pfh, b0h + 2);
                mma16816(o2, pfh, b1h);  mma16816(o3, pfh, b1h + 2);
                mma16816(o0, pfl, b0h);  mma16816(o1, pfl, b0h + 2);
                mma16816(o2, pfl, b1h);  mma16816(o3, pfl, b1h + 2);
                mma16816(o0, pfh, b0l);  mma16816(o1, pfh, b0l + 2);
                mma16816(o2, pfh, b1l);  mma16816(o3, pfh, b1l + 2);
            }
        }
    }

    // ---- epilogue ----
    lsum0 += __shfl_xor_sync(0xffffffffu, lsum0, 1);
    lsum0 += __shfl_xor_sync(0xffffffffu, lsum0, 2);
    lsum1 += __shfl_xor_sync(0xffffffffu, lsum1, 1);
    lsum1 += __shfl_xor_sync(0xffffffffu, lsum1, 2);
    float inv0 = v0 ? (1.f / lsum0) : 0.f;
    float inv1 = v1 ? (1.f / lsum1) : 0.f;

    #pragma unroll
    for (int n = 0; n < 16; n++) {
        int c = n * 8 + (lane & 3) * 2;
        float2* p0 = (float2*)(og + (size_t)r0l * CDIM + c);
        float2* p1 = (float2*)(og + (size_t)(r0l + 8) * CDIM + c);
        *p0 = make_float2(oacc[n][0] * inv0, oacc[n][1] * inv0);
        *p1 = make_float2(oacc[n][2] * inv1, oacc[n][3] * inv1);
    }
}

// ============================================================================
extern "C" void kernel_launch(void* const* d_in, const int* in_sizes, int n_in,
                              void* d_out, int out_size)
{
    const float* x  = (const float*)d_in[0];
    const int*   vl = (const int*)  d_in[1];
    const float* qw = (const float*)d_in[2];
    const float* qb = (const float*)d_in[3];
    const float* kw = (const float*)d_in[4];
    const float* kb = (const float*)d_in[5];
    const float* vw = (const float*)d_in[6];
    const float* vb = (const float*)d_in[7];
    float* out = (float*)d_out;

    cudaFuncSetAttribute(qkv_mma,  cudaFuncAttributeMaxDynamicSharedMemorySize, QKV_SMEM);
    cudaFuncSetAttribute(attn_mma, cudaFuncAttributeMaxDynamicSharedMemorySize, ATT_SMEM);

    qkv_mma<<<(BATCH * SEQ) / 128, 256, QKV_SMEM>>>(x, vl, qw, qb, kw, kb, vw, vb);
    dim3 grid(SEQ / 128, BATCH);
    attn_mma<<<grid, 256, ATT_SMEM>>>(vl, out);
}

// round 12
// speedup vs baseline: 1.1344x; 1.1276x over previous
#include <cuda_runtime.h>
#include <cuda_fp16.h>
#include <math.h>
#include <stdint.h>

#define BATCH 64
#define SEQ   1024
#define CDIM  128
#define NEGM  -1e30f

// fp16 scratch (zero-initialized device globals):
// Q,K hi/lo row-major [b*n][c]; V single fp16 transposed [b][c][n]
__device__ __align__(16) unsigned short g_Qh[BATCH * SEQ * CDIM];
__device__ __align__(16) unsigned short g_Ql[BATCH * SEQ * CDIM];
__device__ __align__(16) unsigned short g_Kh[BATCH * SEQ * CDIM];
__device__ __align__(16) unsigned short g_Kl[BATCH * SEQ * CDIM];
__device__ __align__(16) unsigned short g_Vt[BATCH * CDIM * SEQ];

// ---------------- helpers ----------------
static __device__ __forceinline__ uint32_t smem_u32(const void* p) {
    uint32_t a;
    asm("{ .reg .u64 t; cvta.to.shared.u64 t, %1; cvt.u32.u64 %0, t; }" : "=r"(a) : "l"(p));
    return a;
}
static __device__ __forceinline__ void ldmx4(uint32_t a, uint32_t* r) {
    asm volatile("ldmatrix.sync.aligned.m8n8.x4.shared.b16 {%0,%1,%2,%3}, [%4];"
                 : "=r"(r[0]), "=r"(r[1]), "=r"(r[2]), "=r"(r[3]) : "r"(a));
}
// fp16 MMA, fp32 accumulate
static __device__ __forceinline__ void mmah(float* d, const uint32_t* a, const uint32_t* b) {
    asm volatile("mma.sync.aligned.m16n8k16.row.col.f32.f16.f16.f32 "
                 "{%0,%1,%2,%3}, {%4,%5,%6,%7}, {%8,%9}, {%0,%1,%2,%3};"
                 : "+f"(d[0]), "+f"(d[1]), "+f"(d[2]), "+f"(d[3])
                 : "r"(a[0]), "r"(a[1]), "r"(a[2]), "r"(a[3]), "r"(b[0]), "r"(b[1]));
}
static __device__ __forceinline__ uint32_t cvt2h(float lo, float hi) {
    __half2 h = __floats2half2_rn(lo, hi);
    return reinterpret_cast<uint32_t&>(h);
}
static __device__ __forceinline__ float lo_hf(uint32_t u) {
    __half2 h = reinterpret_cast<__half2&>(u);
    return __low2float(h);
}
static __device__ __forceinline__ float hi_hf(uint32_t u) {
    __half2 h = reinterpret_cast<__half2&>(u);
    return __high2float(h);
}
#define CP16(d, s) asm volatile("cp.async.cg.shared.global [%0], [%1], 16;" :: "r"(d), "l"(s))
#define CP_COMMIT() asm volatile("cp.async.commit_group;" ::: "memory")

#define TS 272                    // stride: 256B-row tiles (Q/K/X/W)
#define VS 144                    // stride: 128B-row tiles (V^T stages)

// ---- attn smem: 3 rotating stage buffers; Q staged in buf1/buf2 at prologue ----
#define SSZ    53248              // stage: KH 17408 | KL 17408 | VH 18432
#define S_KH   0
#define S_KL   17408
#define S_VH   34816
#define ATT_SMEM (3 * SSZ)        // 159744

// ---- qkv smem layout ----
#define X_H    0
#define X_L    34816
#define W_H    69632
#define W_L    104448
#define QKV_SMEM 139264

// loaders (256 threads each)
static __device__ __forceinline__ void loadQ128(uint32_t sdst, const unsigned short* g, int tid) {
    #pragma unroll
    for (int i = 0; i < 8; i++) {
        int idx = tid + (i << 8);
        int r = idx >> 4, c = idx & 15;
        CP16(sdst + (uint32_t)r * TS + (uint32_t)c * 16, (const void*)(g + (size_t)r * CDIM + (c << 3)));
    }
}
static __device__ __forceinline__ void loadK64(uint32_t sdst, const unsigned short* g, int tid) {
    #pragma unroll
    for (int i = 0; i < 4; i++) {
        int idx = tid + (i << 8);
        int r = idx >> 4, c = idx & 15;
        CP16(sdst + (uint32_t)r * TS + (uint32_t)c * 16, (const void*)(g + (size_t)r * CDIM + (c << 3)));
    }
}
static __device__ __forceinline__ void loadV128x64(uint32_t sdst, const unsigned short* g, int tid) {
    #pragma unroll
    for (int i = 0; i < 4; i++) {
        int idx = tid + (i << 8);
        int r = idx >> 3, c = idx & 7;
        CP16(sdst + (uint32_t)r * VS + (uint32_t)c * 16, (const void*)(g + (size_t)r * SEQ + (c << 3)));
    }
}
static __device__ __forceinline__ void stage_load(uint32_t buf, size_t kbase, size_t vbase,
                                                  int kt, int tid) {
    loadK64(buf + S_KH, g_Kh + kbase + (size_t)kt * 64 * CDIM, tid);
    loadK64(buf + S_KL, g_Kl + kbase + (size_t)kt * 64 * CDIM, tid);
    loadV128x64(buf + S_VH, g_Vt + vbase + (size_t)kt * 64, tid);
}

// ============================================================================
// Kernel 1: QKV projection via fp16 mma.sync, 3-term split.
// Q,K -> fp16 hi/lo; V -> single fp16, directly transposed.
// ============================================================================
__global__ __launch_bounds__(256)
void qkv_mma(const float* __restrict__ x, const int* __restrict__ vls,
             const float* __restrict__ qw, const float* __restrict__ qb,
             const float* __restrict__ kw, const float* __restrict__ kb,
             const float* __restrict__ vw, const float* __restrict__ vb)
{
    extern __shared__ __align__(16) char sm[];
    const uint32_t sb = smem_u32(sm);
    const int tid = threadIdx.x, wid = tid >> 5, lane = tid & 31;
    const int row0 = blockIdx.x * 128;
    const int b = row0 >> 10, n0 = row0 & 1023;
    if (n0 >= vls[b]) return;

    const float4* xg = (const float4*)(x + (size_t)row0 * CDIM);
    #pragma unroll
    for (int i = 0; i < 16; i++) {
        int idx = tid + (i << 8);
        int r = idx >> 5, c4 = idx & 31;
        float4 v = xg[r * 32 + c4];
        uint32_t h0 = cvt2h(v.x, v.y), h1 = cvt2h(v.z, v.w);
        uint32_t l0 = cvt2h(v.x - lo_hf(h0), v.y - hi_hf(h0));
        uint32_t l1 = cvt2h(v.z - lo_hf(h1), v.w - hi_hf(h1));
        uint32_t ad = (uint32_t)r * TS + (uint32_t)c4 * 8;
        *(uint2*)(sm + X_H + ad) = make_uint2(h0, h1);
        *(uint2*)(sm + X_L + ad) = make_uint2(l0, l1);
    }

    const uint32_t qrow = (uint32_t)(wid * 16 + (lane & 15)) * TS + ((lane >> 4) & 1) * 16;
    const uint32_t brow = (uint32_t)(lane & 7) * TS + ((lane >> 3) & 1) * 16;
    const int r0l = wid * 16 + (lane >> 2);

    for (int w = 0; w < 3; w++) {
        const float* W  = (w == 0) ? qw : (w == 1) ? kw : vw;
        const float* Bs = (w == 0) ? qb : (w == 1) ? kb : vb;
        __syncthreads();
        const float4* wg = (const float4*)W;
        #pragma unroll
        for (int i = 0; i < 16; i++) {
            int idx = tid + (i << 8);
            int r = idx >> 5, c4 = idx & 31;
            float4 v = wg[r * 32 + c4];
            uint32_t h0 = cvt2h(v.x, v.y), h1 = cvt2h(v.z, v.w);
            uint32_t l0 = cvt2h(v.x - lo_hf(h0), v.y - hi_hf(h0));
            uint32_t l1 = cvt2h(v.z - lo_hf(h1), v.w - hi_hf(h1));
            uint32_t ad = (uint32_t)r * TS + (uint32_t)c4 * 8;
            *(uint2*)(sm + W_H + ad) = make_uint2(h0, h1);
            *(uint2*)(sm + W_L + ad) = make_uint2(l0, l1);
        }
        __syncthreads();

        const uint32_t Ah = sb + ((w < 2) ? X_H : W_H), Al = sb + ((w < 2) ? X_L : W_L);
        const uint32_t Bh = sb + ((w < 2) ? W_H : X_H), Bl = sb + ((w < 2) ? W_L : X_L);

        float acc[16][4];
        #pragma unroll
        for (int n = 0; n < 16; n++)
            #pragma unroll
            for (int q = 0; q < 4; q++) acc[n][q] = 0.f;

        #pragma unroll
        for (int ks = 0; ks < 8; ks++) {
            uint32_t ah[4], al[4];
            ldmx4(Ah + qrow + ks * 32, ah);
            ldmx4(Al + qrow + ks * 32, al);
            #pragma unroll
            for (int n = 0; n < 16; n++) {
                uint32_t bh[2], bl[2];
                uint32_t off = brow + (uint32_t)n * (8 * TS) + ks * 32;
                asm volatile("ldmatrix.sync.aligned.m8n8.x2.shared.b16 {%0,%1}, [%2];"
                             : "=r"(bh[0]), "=r"(bh[1]) : "r"(Bh + off));
                asm volatile("ldmatrix.sync.aligned.m8n8.x2.shared.b16 {%0,%1}, [%2];"
                             : "=r"(bl[0]), "=r"(bl[1]) : "r"(Bl + off));
                mmah(acc[n], ah, bh);
                mmah(acc[n], al, bh);
                mmah(acc[n], ah, bl);
            }
        }

        if (w < 2) {
            unsigned short* Oh = (w == 0) ? g_Qh : g_Kh;
            unsigned short* Ol = (w == 0) ? g_Ql : g_Kl;
            size_t rA = (size_t)(row0 + r0l) * CDIM;
            size_t rB = (size_t)(row0 + r0l + 8) * CDIM;
            #pragma unroll
            for (int n = 0; n < 16; n++) {
                int c = n * 8 + (lane & 3) * 2;
                float b0 = __ldg(Bs + c), b1 = __ldg(Bs + c + 1);
                float v00 = acc[n][0] + b0, v01 = acc[n][1] + b1;
                float v10 = acc[n][2] + b0, v11 = acc[n][3] + b1;
                uint32_t hA = cvt2h(v00, v01), hB = cvt2h(v10, v11);
                *(uint32_t*)(Oh + rA + c) = hA;
                *(uint32_t*)(Oh + rB + c) = hB;
                *(uint32_t*)(Ol + rA + c) = cvt2h(v00 - lo_hf(hA), v01 - hi_hf(hA));
                *(uint32_t*)(Ol + rB + c) = cvt2h(v10 - lo_hf(hB), v11 - hi_hf(hB));
            }
        } else {
            // rows = channels, cols = tokens -> natural V^T write, single fp16
            float bc0 = __ldg(Bs + r0l), bc1 = __ldg(Bs + r0l + 8);
            size_t rA = (size_t)b * CDIM * SEQ + (size_t)r0l * SEQ + n0;
            size_t rB = rA + (size_t)8 * SEQ;
            #pragma unroll
            for (int n = 0; n < 16; n++) {
                int c = n * 8 + (lane & 3) * 2;
                *(uint32_t*)(g_Vt + rA + c) = cvt2h(acc[n][0] + bc0, acc[n][1] + bc0);
                *(uint32_t*)(g_Vt + rB + c) = cvt2h(acc[n][2] + bc1, acc[n][3] + bc1);
            }
        }
    }
}

// ============================================================================
// Kernel 2: fp16 flash attention. S = 3-term split (192 MMA/stage);
// masked-before-max online softmax; PV single-term fp16 (64 MMA/stage).
// ============================================================================
__global__ __launch_bounds__(256)
void attn_mma(const int* __restrict__ vls, float* __restrict__ out)
{
    extern __shared__ __align__(16) char sm[];
    const uint32_t sb = smem_u32(sm);
    const int tid = threadIdx.x, wid = tid >> 5, lane = tid & 31;
    const int b = blockIdx.y;
    const int row0 = (gridDim.x - 1 - blockIdx.x) * 128;   // heavy tiles first
    const int vl = vls[b];
    float* og = out + ((size_t)b * SEQ + row0) * CDIM;

    if (row0 >= vl) {
        float4 z = make_float4(0.f, 0.f, 0.f, 0.f);
        float4* o4 = (float4*)og;
        for (int i = tid; i < 128 * 32; i += 256) o4[i] = z;
        return;
    }

    const uint32_t qrow = (uint32_t)(wid * 16 + (lane & 15)) * TS + ((lane >> 4) & 1) * 16;
    const uint32_t brwK = (uint32_t)((lane & 7) + ((lane >> 4) << 3)) * TS + ((lane >> 3) & 1) * 16;
    const uint32_t brwV = (uint32_t)((lane & 7) + ((lane >> 4) << 3)) * VS + ((lane >> 3) & 1) * 16;
    const int r0l = wid * 16 + (lane >> 2);
    const bool v0 = row0 + r0l < vl, v1 = row0 + r0l + 8 < vl;

    const size_t kbase = (size_t)b * SEQ * CDIM;
    const size_t vbase = (size_t)b * CDIM * SEQ;
    const int nst = (vl + 63) >> 6;
    const uint32_t buf0 = sb, buf1 = sb + SSZ, buf2 = sb + 2 * SSZ;

    // prologue: Qh->buf1, Ql->buf2 (G0); s0->buf0 (G1)
    loadQ128(buf1, g_Qh + kbase + (size_t)row0 * CDIM, tid);
    loadQ128(buf2, g_Ql + kbase + (size_t)row0 * CDIM, tid);
    CP_COMMIT();
    stage_load(buf0, kbase, vbase, 0, tid);
    CP_COMMIT();
    asm volatile("cp.async.wait_group 1;" ::: "memory");   // Q resident
    __syncthreads();

    uint32_t qh[8][4], ql[8][4];
    #pragma unroll
    for (int ks = 0; ks < 8; ks++) {
        ldmx4(buf1 + qrow + ks * 32, qh[ks]);
        ldmx4(buf2 + qrow + ks * 32, ql[ks]);
    }
    __syncthreads();                                        // Q reads done everywhere
    if (nst > 1) stage_load(buf1, kbase, vbase, 1, tid);
    CP_COMMIT();                                            // G2 (real or empty)

    float oacc[16][4];
    #pragma unroll
    for (int n = 0; n < 16; n++)
        #pragma unroll
        for (int q = 0; q < 4; q++) oacc[n][q] = 0.f;
    float lsum0 = 0.f, lsum1 = 0.f;
    float m0 = NEGM, m1 = NEGM;

    for (int t = 0; t < nst; t++) {
        asm volatile("cp.async.wait_group 1;" ::: "memory");   // stage t resident
        __syncthreads();
        if (t + 2 < nst) {
            uint32_t pb = ((t + 2) % 3 == 0) ? buf0 : ((t + 2) % 3 == 1) ? buf1 : buf2;
            stage_load(pb, kbase, vbase, t + 2, tid);
        }
        CP_COMMIT();

        const uint32_t st = (t % 3 == 0) ? buf0 : (t % 3 == 1) ? buf1 : buf2;

        // ---- S = Q K^T (fp16, 3 split terms) ----
        float sacc[8][4];
        #pragma unroll
        for (int n = 0; n < 8; n++)
            #pragma unroll
            for (int q = 0; q < 4; q++) sacc[n][q] = 0.f;

        #pragma unroll
        for (int ks = 0; ks < 8; ks++) {
            #pragma unroll
            for (int g = 0; g < 2; g++) {
                uint32_t b0h[4], b0l[4], b1h[4], b1l[4];
                uint32_t off0 = brwK + (uint32_t)(2 * g)     * (16 * TS) + ks * 32;
                uint32_t off1 = brwK + (uint32_t)(2 * g + 1) * (16 * TS) + ks * 32;
                ldmx4(st + S_KH + off0, b0h);
                ldmx4(st + S_KL + off0, b0l);
                ldmx4(st + S_KH + off1, b1h);
                ldmx4(st + S_KL + off1, b1l);
                float* a0 = sacc[4 * g + 0];
                float* a1 = sacc[4 * g + 1];
                float* a2 = sacc[4 * g + 2];
                float* a3 = sacc[4 * g + 3];
                mmah(a0, qh[ks], b0h);  mmah(a1, qh[ks], b0h + 2);
                mmah(a2, qh[ks], b1h);  mmah(a3, qh[ks], b1h + 2);
                mmah(a0, ql[ks], b0h);  mmah(a1, ql[ks], b0h + 2);
                mmah(a2, ql[ks], b1h);  mmah(a3, ql[ks], b1h + 2);
                mmah(a0, qh[ks], b0l);  mmah(a1, qh[ks], b0l + 2);
                mmah(a2, qh[ks], b1l);  mmah(a3, qh[ks], b1l + 2);
            }
        }

        // ---- mask BEFORE max (masked cols carry real scores!) ----
        const int cb = t * 64;
        #pragma unroll
        for (int n = 0; n < 8; n++) {
            int c0 = cb + n * 8 + (lane & 3) * 2;
            if (c0 >= vl)     { sacc[n][0] = NEGM; sacc[n][2] = NEGM; }
            if (c0 + 1 >= vl) { sacc[n][1] = NEGM; sacc[n][3] = NEGM; }
        }

        // ---- online max + rescale ----
        float tm0 = NEGM, tm1 = NEGM;
        #pragma unroll
        for (int n = 0; n < 8; n++) {
            tm0 = fmaxf(tm0, fmaxf(sacc[n][0], sacc[n][1]));
            tm1 = fmaxf(tm1, fmaxf(sacc[n][2], sacc[n][3]));
        }
        tm0 = fmaxf(tm0, __shfl_xor_sync(0xffffffffu, tm0, 1));
        tm0 = fmaxf(tm0, __shfl_xor_sync(0xffffffffu, tm0, 2));
        tm1 = fmaxf(tm1, __shfl_xor_sync(0xffffffffu, tm1, 1));
        tm1 = fmaxf(tm1, __shfl_xor_sync(0xffffffffu, tm1, 2));
        float mn0 = fmaxf(m0, tm0), mn1 = fmaxf(m1, tm1);
        float sc0 = __expf(m0 - mn0), sc1 = __expf(m1 - mn1);
        m0 = mn0; m1 = mn1;
        lsum0 *= sc0; lsum1 *= sc1;
        #pragma unroll
        for (int n = 0; n < 16; n++) {
            oacc[n][0] *= sc0; oacc[n][1] *= sc0;
            oacc[n][2] *= sc1; oacc[n][3] *= sc1;
        }

        // ---- p = exp(s - m); masked cols -> exp(-huge) = 0 naturally ----
        #pragma unroll
        for (int n = 0; n < 8; n++) {
            float e0 = v0 ? __expf(sacc[n][0] - m0) : 0.f;
            float e1 = v0 ? __expf(sacc[n][1] - m0) : 0.f;
            float e2 = v1 ? __expf(sacc[n][2] - m1) : 0.f;
            float e3 = v1 ? __expf(sacc[n][3] - m1) : 0.f;
            lsum0 += e0 + e1;
            lsum1 += e2 + e3;
            sacc[n][0] = e0; sacc[n][1] = e1; sacc[n][2] = e2; sacc[n][3] = e3;
        }

        // ---- O += P V (single fp16 term) ----
        #pragma unroll
        for (int ks = 0; ks < 4; ks++) {
            const float* t0 = sacc[2 * ks];
            const float* t1 = sacc[2 * ks + 1];
            uint32_t pf[4];
            pf[0] = cvt2h(t0[0], t0[1]);
            pf[1] = cvt2h(t0[2], t0[3]);
            pf[2] = cvt2h(t1[0], t1[1]);
            pf[3] = cvt2h(t1[2], t1[3]);
            #pragma unroll
            for (int g = 0; g < 4; g++) {
                uint32_t b0[4], b1[4];
                uint32_t off0 = brwV + (uint32_t)(2 * g)     * (16 * VS) + ks * 32;
                uint32_t off1 = brwV + (uint32_t)(2 * g + 1) * (16 * VS) + ks * 32;
                ldmx4(st + S_VH + off0, b0);
                ldmx4(st + S_VH + off1, b1);
                mmah(oacc[4 * g + 0], pf, b0);  mmah(oacc[4 * g + 1], pf, b0 + 2);
                mmah(oacc[4 * g + 2], pf, b1);  mmah(oacc[4 * g + 3], pf, b1 + 2);
            }
        }
    }

    // ---- epilogue ----
    lsum0 += __shfl_xor_sync(0xffffffffu, lsum0, 1);
    lsum0 += __shfl_xor_sync(0xffffffffu, lsum0, 2);
    lsum1 += __shfl_xor_sync(0xffffffffu, lsum1, 1);
    lsum1 += __shfl_xor_sync(0xffffffffu, lsum1, 2);
    float inv0 = v0 ? (1.f / lsum0) : 0.f;
    float inv1 = v1 ? (1.f / lsum1) : 0.f;

    #pragma unroll
    for (int n = 0; n < 16; n++) {
        int c = n * 8 + (lane & 3) * 2;
        float2* p0 = (float2*)(og + (size_t)r0l * CDIM + c);
        float2* p1 = (float2*)(og + (size_t)(r0l + 8) * CDIM + c);
        *p0 = make_float2(oacc[n][0] * inv0, oacc[n][1] * inv0);
        *p1 = make_float2(oacc[n][2] * inv1, oacc[n][3] * inv1);
    }
}

// ============================================================================
extern "C" void kernel_launch(void* const* d_in, const int* in_sizes, int n_in,
                              void* d_out, int out_size)
{
    const float* x  = (const float*)d_in[0];
    const int*   vl = (const int*)  d_in[1];
    const float* qw = (const float*)d_in[2];
    const float* qb = (const float*)d_in[3];
    const float* kw = (const float*)d_in[4];
    const float* kb = (const float*)d_in[5];
    const float* vw = (const float*)d_in[6];
    const float* vb = (const float*)d_in[7];
    float* out = (float*)d_out;

    cudaFuncSetAttribute(qkv_mma,  cudaFuncAttributeMaxDynamicSharedMemorySize, QKV_SMEM);
    cudaFuncSetAttribute(attn_mma, cudaFuncAttributeMaxDynamicSharedMemorySize, ATT_SMEM);

    qkv_mma<<<(BATCH * SEQ) / 128, 256, QKV_SMEM>>>(x, vl, qw, qb, kw, kb, vw, vb);
    dim3 grid(SEQ / 128, BATCH);
    attn_mma<<<grid, 256, ATT_SMEM>>>(vl, out);
}

// round 13
// speedup vs baseline: 1.2432x; 1.0959x over previous
#include <cuda_runtime.h>
#include <cuda_fp16.h>
#include <math.h>
#include <stdint.h>

#define BATCH 64
#define SEQ   1024
#define CDIM  128
#define NEGM  -1e30f

// fp16 scratch (zero-initialized device globals):
// Q,K hi/lo row-major [b*n][c]; V single fp16 transposed [b][c][n]
__device__ __align__(16) unsigned short g_Qh[BATCH * SEQ * CDIM];
__device__ __align__(16) unsigned short g_Ql[BATCH * SEQ * CDIM];
__device__ __align__(16) unsigned short g_Kh[BATCH * SEQ * CDIM];
__device__ __align__(16) unsigned short g_Kl[BATCH * SEQ * CDIM];
__device__ __align__(16) unsigned short g_Vt[BATCH * CDIM * SEQ];

// ---------------- helpers ----------------
static __device__ __forceinline__ uint32_t smem_u32(const void* p) {
    uint32_t a;
    asm("{ .reg .u64 t; cvta.to.shared.u64 t, %1; cvt.u32.u64 %0, t; }" : "=r"(a) : "l"(p));
    return a;
}
static __device__ __forceinline__ void ldmx4(uint32_t a, uint32_t* r) {
    asm volatile("ldmatrix.sync.aligned.m8n8.x4.shared.b16 {%0,%1,%2,%3}, [%4];"
                 : "=r"(r[0]), "=r"(r[1]), "=r"(r[2]), "=r"(r[3]) : "r"(a));
}
// fp16 MMA, fp32 accumulate
static __device__ __forceinline__ void mmah(float* d, const uint32_t* a, const uint32_t* b) {
    asm volatile("mma.sync.aligned.m16n8k16.row.col.f32.f16.f16.f32 "
                 "{%0,%1,%2,%3}, {%4,%5,%6,%7}, {%8,%9}, {%0,%1,%2,%3};"
                 : "+f"(d[0]), "+f"(d[1]), "+f"(d[2]), "+f"(d[3])
                 : "r"(a[0]), "r"(a[1]), "r"(a[2]), "r"(a[3]), "r"(b[0]), "r"(b[1]));
}
static __device__ __forceinline__ uint32_t cvt2h(float lo, float hi) {
    __half2 h = __floats2half2_rn(lo, hi);
    return reinterpret_cast<uint32_t&>(h);
}
static __device__ __forceinline__ float lo_hf(uint32_t u) {
    __half2 h = reinterpret_cast<__half2&>(u);
    return __low2float(h);
}
static __device__ __forceinline__ float hi_hf(uint32_t u) {
    __half2 h = reinterpret_cast<__half2&>(u);
    return __high2float(h);
}
#define CP16(d, s) asm volatile("cp.async.cg.shared.global [%0], [%1], 16;" :: "r"(d), "l"(s))
#define CP_COMMIT() asm volatile("cp.async.commit_group;" ::: "memory")
#define CP_WAIT0()  asm volatile("cp.async.wait_group 0;" ::: "memory")

#define TS 272                    // stride for 256B-row tiles

// ---- attn smem: 2 buffers of 128-key stages; Q staged in buf1 at prologue ----
#define S_KH   0
#define S_KL   34816
#define S_V    69632
#define SSZ    104448             // KH + KL + V (each 128 x 272)
#define ATT_SMEM (2 * SSZ)        // 208896

// ---- qkv smem layout ----
#define X_H    0
#define X_L    34816
#define W_H    69632
#define W_L    104448
#define QKV_SMEM 139264

// generic 128-row x 256B tile loader (256 threads)
static __device__ __forceinline__ void loadT(uint32_t sdst, const unsigned short* g,
                                             int gstride, int tid) {
    #pragma unroll
    for (int i = 0; i < 8; i++) {
        int idx = tid + (i << 8);
        int r = idx >> 4, c = idx & 15;
        CP16(sdst + (uint32_t)r * TS + (uint32_t)c * 16, (const void*)(g + (size_t)r * gstride + (c << 3)));
    }
}
static __device__ __forceinline__ void stage_load(uint32_t buf, size_t kbase, size_t vbase,
                                                  int kt, int tid) {
    loadT(buf + S_KH, g_Kh + kbase + (size_t)kt * 128 * CDIM, CDIM, tid);
    loadT(buf + S_KL, g_Kl + kbase + (size_t)kt * 128 * CDIM, CDIM, tid);
    loadT(buf + S_V,  g_Vt + vbase + (size_t)kt * 128, SEQ, tid);
}

// ============================================================================
// Kernel 1: QKV projection via fp16 mma.sync, 3-term split (round-12 version).
// ============================================================================
__global__ __launch_bounds__(256)
void qkv_mma(const float* __restrict__ x, const int* __restrict__ vls,
             const float* __restrict__ qw, const float* __restrict__ qb,
             const float* __restrict__ kw, const float* __restrict__ kb,
             const float* __restrict__ vw, const float* __restrict__ vb)
{
    extern __shared__ __align__(16) char sm[];
    const uint32_t sb = smem_u32(sm);
    const int tid = threadIdx.x, wid = tid >> 5, lane = tid & 31;
    const int row0 = blockIdx.x * 128;
    const int b = row0 >> 10, n0 = row0 & 1023;
    if (n0 >= vls[b]) return;

    const float4* xg = (const float4*)(x + (size_t)row0 * CDIM);
    #pragma unroll
    for (int i = 0; i < 16; i++) {
        int idx = tid + (i << 8);
        int r = idx >> 5, c4 = idx & 31;
        float4 v = xg[r * 32 + c4];
        uint32_t h0 = cvt2h(v.x, v.y), h1 = cvt2h(v.z, v.w);
        uint32_t l0 = cvt2h(v.x - lo_hf(h0), v.y - hi_hf(h0));
        uint32_t l1 = cvt2h(v.z - lo_hf(h1), v.w - hi_hf(h1));
        uint32_t ad = (uint32_t)r * TS + (uint32_t)c4 * 8;
        *(uint2*)(sm + X_H + ad) = make_uint2(h0, h1);
        *(uint2*)(sm + X_L + ad) = make_uint2(l0, l1);
    }

    const uint32_t qrow = (uint32_t)(wid * 16 + (lane & 15)) * TS + ((lane >> 4) & 1) * 16;
    const uint32_t brow = (uint32_t)(lane & 7) * TS + ((lane >> 3) & 1) * 16;
    const int r0l = wid * 16 + (lane >> 2);

    for (int w = 0; w < 3; w++) {
        const float* W  = (w == 0) ? qw : (w == 1) ? kw : vw;
        const float* Bs = (w == 0) ? qb : (w == 1) ? kb : vb;
        __syncthreads();
        const float4* wg = (const float4*)W;
        #pragma unroll
        for (int i = 0; i < 16; i++) {
            int idx = tid + (i << 8);
            int r = idx >> 5, c4 = idx & 31;
            float4 v = wg[r * 32 + c4];
            uint32_t h0 = cvt2h(v.x, v.y), h1 = cvt2h(v.z, v.w);
            uint32_t l0 = cvt2h(v.x - lo_hf(h0), v.y - hi_hf(h0));
            uint32_t l1 = cvt2h(v.z - lo_hf(h1), v.w - hi_hf(h1));
            uint32_t ad = (uint32_t)r * TS + (uint32_t)c4 * 8;
            *(uint2*)(sm + W_H + ad) = make_uint2(h0, h1);
            *(uint2*)(sm + W_L + ad) = make_uint2(l0, l1);
        }
        __syncthreads();

        const uint32_t Ah = sb + ((w < 2) ? X_H : W_H), Al = sb + ((w < 2) ? X_L : W_L);
        const uint32_t Bh = sb + ((w < 2) ? W_H : X_H), Bl = sb + ((w < 2) ? W_L : X_L);

        float acc[16][4];
        #pragma unroll
        for (int n = 0; n < 16; n++)
            #pragma unroll
            for (int q = 0; q < 4; q++) acc[n][q] = 0.f;

        #pragma unroll
        for (int ks = 0; ks < 8; ks++) {
            uint32_t ah[4], al[4];
            ldmx4(Ah + qrow + ks * 32, ah);
            ldmx4(Al + qrow + ks * 32, al);
            #pragma unroll
            for (int n = 0; n < 16; n++) {
                uint32_t bh[2], bl[2];
                uint32_t off = brow + (uint32_t)n * (8 * TS) + ks * 32;
                asm volatile("ldmatrix.sync.aligned.m8n8.x2.shared.b16 {%0,%1}, [%2];"
                             : "=r"(bh[0]), "=r"(bh[1]) : "r"(Bh + off));
                asm volatile("ldmatrix.sync.aligned.m8n8.x2.shared.b16 {%0,%1}, [%2];"
                             : "=r"(bl[0]), "=r"(bl[1]) : "r"(Bl + off));
                mmah(acc[n], ah, bh);
                mmah(acc[n], al, bh);
                mmah(acc[n], ah, bl);
            }
        }

        if (w < 2) {
            unsigned short* Oh = (w == 0) ? g_Qh : g_Kh;
            unsigned short* Ol = (w == 0) ? g_Ql : g_Kl;
            size_t rA = (size_t)(row0 + r0l) * CDIM;
            size_t rB = (size_t)(row0 + r0l + 8) * CDIM;
            #pragma unroll
            for (int n = 0; n < 16; n++) {
                int c = n * 8 + (lane & 3) * 2;
                float b0 = __ldg(Bs + c), b1 = __ldg(Bs + c + 1);
                float v00 = acc[n][0] + b0, v01 = acc[n][1] + b1;
                float v10 = acc[n][2] + b0, v11 = acc[n][3] + b1;
                uint32_t hA = cvt2h(v00, v01), hB = cvt2h(v10, v11);
                *(uint32_t*)(Oh + rA + c) = hA;
                *(uint32_t*)(Oh + rB + c) = hB;
                *(uint32_t*)(Ol + rA + c) = cvt2h(v00 - lo_hf(hA), v01 - hi_hf(hA));
                *(uint32_t*)(Ol + rB + c) = cvt2h(v10 - lo_hf(hB), v11 - hi_hf(hB));
            }
        } else {
            float bc0 = __ldg(Bs + r0l), bc1 = __ldg(Bs + r0l + 8);
            size_t rA = (size_t)b * CDIM * SEQ + (size_t)r0l * SEQ + n0;
            size_t rB = rA + (size_t)8 * SEQ;
            #pragma unroll
            for (int n = 0; n < 16; n++) {
                int c = n * 8 + (lane & 3) * 2;
                *(uint32_t*)(g_Vt + rA + c) = cvt2h(acc[n][0] + bc0, acc[n][1] + bc0);
                *(uint32_t*)(g_Vt + rB + c) = cvt2h(acc[n][2] + bc1, acc[n][3] + bc1);
            }
        }
    }
}

// ============================================================================
// Kernel 2: fp16 flash attention, 128-key double-buffered stages,
// masked-before-max online softmax with vote-guarded rescale.
// ============================================================================
__global__ __launch_bounds__(256)
void attn_mma(const int* __restrict__ vls, float* __restrict__ out)
{
    extern __shared__ __align__(16) char sm[];
    const uint32_t sb = smem_u32(sm);
    const int tid = threadIdx.x, wid = tid >> 5, lane = tid & 31;
    const int b = blockIdx.y;
    const int row0 = (gridDim.x - 1 - blockIdx.x) * 128;   // heavy tiles first
    const int vl = vls[b];
    float* og = out + ((size_t)b * SEQ + row0) * CDIM;

    if (row0 >= vl) {
        float4 z = make_float4(0.f, 0.f, 0.f, 0.f);
        float4* o4 = (float4*)og;
        for (int i = tid; i < 128 * 32; i += 256) o4[i] = z;
        return;
    }

    const uint32_t qrow = (uint32_t)(wid * 16 + (lane & 15)) * TS + ((lane >> 4) & 1) * 16;
    const uint32_t brw  = (uint32_t)((lane & 7) + ((lane >> 4) << 3)) * TS + ((lane >> 3) & 1) * 16;
    const int r0l = wid * 16 + (lane >> 2);
    const bool v0 = row0 + r0l < vl, v1 = row0 + r0l + 8 < vl;

    const size_t kbase = (size_t)b * SEQ * CDIM;
    const size_t vbase = (size_t)b * CDIM * SEQ;
    const int nst = (vl + 127) >> 7;
    const uint32_t buf0 = sb, buf1 = sb + SSZ;

    // prologue: Q -> buf1, stage0 -> buf0
    loadT(buf1,         g_Qh + kbase + (size_t)row0 * CDIM, CDIM, tid);
    loadT(buf1 + 34816, g_Ql + kbase + (size_t)row0 * CDIM, CDIM, tid);
    stage_load(buf0, kbase, vbase, 0, tid);
    CP_COMMIT();
    CP_WAIT0();
    __syncthreads();

    uint32_t qh[8][4], ql[8][4];
    #pragma unroll
    for (int ks = 0; ks < 8; ks++) {
        ldmx4(buf1 +         qrow + ks * 32, qh[ks]);
        ldmx4(buf1 + 34816 + qrow + ks * 32, ql[ks]);
    }
    __syncthreads();            // all Q reads done before stage1 overwrites buf1

    float oacc[16][4];
    #pragma unroll
    for (int n = 0; n < 16; n++)
        #pragma unroll
        for (int q = 0; q < 4; q++) oacc[n][q] = 0.f;
    float lsum0 = 0.f, lsum1 = 0.f;
    float m0 = NEGM, m1 = NEGM;

    for (int t = 0; t < nst; t++) {
        if (t > 0) {
            CP_WAIT0();          // stage t resident
            __syncthreads();     // all warps past stage t-1 (buffer reuse safe)
        }
        if (t + 1 < nst) {
            stage_load((t & 1) ? buf0 : buf1, kbase, vbase, t + 1, tid);
            CP_COMMIT();
        }
        const uint32_t st = (t & 1) ? buf1 : buf0;

        // ---- S = Q K^T (fp16, 3 split terms), 128 keys ----
        float sacc[16][4];
        #pragma unroll
        for (int n = 0; n < 16; n++)
            #pragma unroll
            for (int q = 0; q < 4; q++) sacc[n][q] = 0.f;

        #pragma unroll
        for (int ks = 0; ks < 8; ks++) {
            #pragma unroll
            for (int g = 0; g < 4; g++) {
                uint32_t b0h[4], b0l[4], b1h[4], b1l[4];
                uint32_t off0 = brw + (uint32_t)(2 * g)     * (16 * TS) + ks * 32;
                uint32_t off1 = brw + (uint32_t)(2 * g + 1) * (16 * TS) + ks * 32;
                ldmx4(st + S_KH + off0, b0h);
                ldmx4(st + S_KL + off0, b0l);
                ldmx4(st + S_KH + off1, b1h);
                ldmx4(st + S_KL + off1, b1l);
                float* a0 = sacc[4 * g + 0];
                float* a1 = sacc[4 * g + 1];
                float* a2 = sacc[4 * g + 2];
                float* a3 = sacc[4 * g + 3];
                mmah(a0, qh[ks], b0h);  mmah(a1, qh[ks], b0h + 2);
                mmah(a2, qh[ks], b1h);  mmah(a3, qh[ks], b1h + 2);
                mmah(a0, ql[ks], b0h);  mmah(a1, ql[ks], b0h + 2);
                mmah(a2, ql[ks], b1h);  mmah(a3, ql[ks], b1h + 2);
                mmah(a0, qh[ks], b0l);  mmah(a1, qh[ks], b0l + 2);
                mmah(a2, qh[ks], b1l);  mmah(a3, qh[ks], b1l + 2);
            }
        }

        // ---- mask BEFORE max (masked cols carry real scores) ----
        const int cb = t * 128;
        #pragma unroll
        for (int n = 0; n < 16; n++) {
            int c0 = cb + n * 8 + (lane & 3) * 2;
            if (c0 >= vl)     { sacc[n][0] = NEGM; sacc[n][2] = NEGM; }
            if (c0 + 1 >= vl) { sacc[n][1] = NEGM; sacc[n][3] = NEGM; }
        }

        // ---- online max, vote-guarded rescale ----
        float tm0 = NEGM, tm1 = NEGM;
        #pragma unroll
        for (int n = 0; n < 16; n++) {
            tm0 = fmaxf(tm0, fmaxf(sacc[n][0], sacc[n][1]));
            tm1 = fmaxf(tm1, fmaxf(sacc[n][2], sacc[n][3]));
        }
        tm0 = fmaxf(tm0, __shfl_xor_sync(0xffffffffu, tm0, 1));
        tm0 = fmaxf(tm0, __shfl_xor_sync(0xffffffffu, tm0, 2));
        tm1 = fmaxf(tm1, __shfl_xor_sync(0xffffffffu, tm1, 1));
        tm1 = fmaxf(tm1, __shfl_xor_sync(0xffffffffu, tm1, 2));
        if (__any_sync(0xffffffffu, tm0 > m0 || tm1 > m1)) {
            float mn0 = fmaxf(m0, tm0), mn1 = fmaxf(m1, tm1);
            float sc0 = __expf(m0 - mn0), sc1 = __expf(m1 - mn1);
            m0 = mn0; m1 = mn1;
            lsum0 *= sc0; lsum1 *= sc1;
            #pragma unroll
            for (int n = 0; n < 16; n++) {
                oacc[n][0] *= sc0; oacc[n][1] *= sc0;
                oacc[n][2] *= sc1; oacc[n][3] *= sc1;
            }
        }

        // ---- p = exp(s - m); masked cols -> 0; rows >= vl zeroed at epilogue ----
        #pragma unroll
        for (int n = 0; n < 16; n++) {
            float e0 = __expf(sacc[n][0] - m0);
            float e1 = __expf(sacc[n][1] - m0);
            float e2 = __expf(sacc[n][2] - m1);
            float e3 = __expf(sacc[n][3] - m1);
            lsum0 += e0 + e1;
            lsum1 += e2 + e3;
            sacc[n][0] = e0; sacc[n][1] = e1; sacc[n][2] = e2; sacc[n][3] = e3;
        }

        // ---- O += P V (single fp16 term), 128 keys ----
        #pragma unroll
        for (int ks = 0; ks < 8; ks++) {
            const float* t0 = sacc[2 * ks];
            const float* t1 = sacc[2 * ks + 1];
            uint32_t pf[4];
            pf[0] = cvt2h(t0[0], t0[1]);
            pf[1] = cvt2h(t0[2], t0[3]);
            pf[2] = cvt2h(t1[0], t1[1]);
            pf[3] = cvt2h(t1[2], t1[3]);
            #pragma unroll
            for (int g = 0; g < 4; g++) {
                uint32_t b0[4], b1[4];
                uint32_t off0 = brw + (uint32_t)(2 * g)     * (16 * TS) + ks * 32;
                uint32_t off1 = brw + (uint32_t)(2 * g + 1) * (16 * TS) + ks * 32;
                ldmx4(st + S_V + off0, b0);
                ldmx4(st + S_V + off1, b1);
                mmah(oacc[4 * g + 0], pf, b0);  mmah(oacc[4 * g + 1], pf, b0 + 2);
                mmah(oacc[4 * g + 2], pf, b1);  mmah(oacc[4 * g + 3], pf, b1 + 2);
            }
        }
    }

    // ---- epilogue ----
    lsum0 += __shfl_xor_sync(0xffffffffu, lsum0, 1);
    lsum0 += __shfl_xor_sync(0xffffffffu, lsum0, 2);
    lsum1 += __shfl_xor_sync(0xffffffffu, lsum1, 1);
    lsum1 += __shfl_xor_sync(0xffffffffu, lsum1, 2);
    float inv0 = v0 ? (1.f / lsum0) : 0.f;
    float inv1 = v1 ? (1.f / lsum1) : 0.f;

    #pragma unroll
    for (int n = 0; n < 16; n++) {
        int c = n * 8 + (lane & 3) * 2;
        float2* p0 = (float2*)(og + (size_t)r0l * CDIM + c);
        float2* p1 = (float2*)(og + (size_t)(r0l + 8) * CDIM + c);
        *p0 = make_float2(oacc[n][0] * inv0, oacc[n][1] * inv0);
        *p1 = make_float2(oacc[n][2] * inv1, oacc[n][3] * inv1);
    }
}

// ============================================================================
extern "C" void kernel_launch(void* const* d_in, const int* in_sizes, int n_in,
                              void* d_out, int out_size)
{
    const float* x  = (const float*)d_in[0];
    const int*   vl = (const int*)  d_in[1];
    const float* qw = (const float*)d_in[2];
    const float* qb = (const float*)d_in[3];
    const float* kw = (const float*)d_in[4];
    const float* kb = (const float*)d_in[5];
    const float* vw = (const float*)d_in[6];
    const float* vb = (const float*)d_in[7];
    float* out = (float*)d_out;

    cudaFuncSetAttribute(qkv_mma,  cudaFuncAttributeMaxDynamicSharedMemorySize, QKV_SMEM);
    cudaFuncSetAttribute(attn_mma, cudaFuncAttributeMaxDynamicSharedMemorySize, ATT_SMEM);

    qkv_mma<<<(BATCH * SEQ) / 128, 256, QKV_SMEM>>>(x, vl, qw, qb, kw, kb, vw, vb);
    dim3 grid(SEQ / 128, BATCH);
    attn_mma<<<grid, 256, ATT_SMEM>>>(vl, out);
}

// round 16
// speedup vs baseline: 1.2774x; 1.0275x over previous
#include <cuda_runtime.h>
#include <cuda_fp16.h>
#include <math.h>
#include <stdint.h>

#define BATCH 64
#define SEQ   1024
#define CDIM  128
#define NEGM  -1e30f
#define LOG2E 1.4426950408889634f

// fp16 scratch (zero-initialized device globals):
// Q (pre-scaled by log2e), K hi/lo row-major [b*n][c]; V single fp16 transposed [b][c][n]
__device__ __align__(16) unsigned short g_Qh[BATCH * SEQ * CDIM];
__device__ __align__(16) unsigned short g_Ql[BATCH * SEQ * CDIM];
__device__ __align__(16) unsigned short g_Kh[BATCH * SEQ * CDIM];
__device__ __align__(16) unsigned short g_Kl[BATCH * SEQ * CDIM];
__device__ __align__(16) unsigned short g_Vt[BATCH * CDIM * SEQ];

// ---------------- helpers ----------------
static __device__ __forceinline__ uint32_t smem_u32(const void* p) {
    uint32_t a;
    asm("{ .reg .u64 t; cvta.to.shared.u64 t, %1; cvt.u32.u64 %0, t; }" : "=r"(a) : "l"(p));
    return a;
}
static __device__ __forceinline__ void ldmx4(uint32_t a, uint32_t* r) {
    asm volatile("ldmatrix.sync.aligned.m8n8.x4.shared.b16 {%0,%1,%2,%3}, [%4];"
                 : "=r"(r[0]), "=r"(r[1]), "=r"(r[2]), "=r"(r[3]) : "r"(a));
}
// fp16 MMA, fp32 accumulate
static __device__ __forceinline__ void mmah(float* d, const uint32_t* a, const uint32_t* b) {
    asm volatile("mma.sync.aligned.m16n8k16.row.col.f32.f16.f16.f32 "
                 "{%0,%1,%2,%3}, {%4,%5,%6,%7}, {%8,%9}, {%0,%1,%2,%3};"
                 : "+f"(d[0]), "+f"(d[1]), "+f"(d[2]), "+f"(d[3])
                 : "r"(a[0]), "r"(a[1]), "r"(a[2]), "r"(a[3]), "r"(b[0]), "r"(b[1]));
}
static __device__ __forceinline__ uint32_t cvt2h(float lo, float hi) {
    __half2 h = __floats2half2_rn(lo, hi);
    return reinterpret_cast<uint32_t&>(h);
}
static __device__ __forceinline__ float lo_hf(uint32_t u) {
    __half2 h = reinterpret_cast<__half2&>(u);
    return __low2float(h);
}
static __device__ __forceinline__ float hi_hf(uint32_t u) {
    __half2 h = reinterpret_cast<__half2&>(u);
    return __high2float(h);
}
#define CP16(d, s) asm volatile("cp.async.cg.shared.global [%0], [%1], 16;" :: "r"(d), "l"(s))
#define CP_COMMIT() asm volatile("cp.async.commit_group;" ::: "memory")
#define CP_WAIT0()  asm volatile("cp.async.wait_group 0;" ::: "memory")

#define TS 272                    // stride for 256B-row tiles

// ---- attn smem: 2 buffers of 128-key stages; Q staged in buf1 at prologue ----
#define S_KH   0
#define S_KL   34816
#define S_V    69632
#define SSZ    104448             // KH + KL + V (each 128 x 272)
#define ATT_SMEM (2 * SSZ)        // 208896

// ---- qkv smem layout ----
#define X_H    0
#define X_L    34816
#define W_H    69632
#define W_L    104448
#define QKV_SMEM 139264

// generic 128-row x 256B tile loader (256 threads)
static __device__ __forceinline__ void loadT(uint32_t sdst, const unsigned short* g,
                                             int gstride, int tid) {
    #pragma unroll
    for (int i = 0; i < 8; i++) {
        int idx = tid + (i << 8);
        int r = idx >> 4, c = idx & 15;
        CP16(sdst + (uint32_t)r * TS + (uint32_t)c * 16, (const void*)(g + (size_t)r * gstride + (c << 3)));
    }
}
static __device__ __forceinline__ void stage_load(uint32_t buf, size_t kbase, size_t vbase,
                                                  int kt, int tid) {
    loadT(buf + S_KH, g_Kh + kbase + (size_t)kt * 128 * CDIM, CDIM, tid);
    loadT(buf + S_KL, g_Kl + kbase + (size_t)kt * 128 * CDIM, CDIM, tid);
    loadT(buf + S_V,  g_Vt + vbase + (size_t)kt * 128, SEQ, tid);
}

// ============================================================================
// Kernel 1: QKV projection via fp16 mma.sync, 3-term split.
// Q output pre-scaled by log2(e) so attention can use exp2 directly.
// ============================================================================
__global__ __launch_bounds__(256)
void qkv_mma(const float* __restrict__ x, const int* __restrict__ vls,
             const float* __restrict__ qw, const float* __restrict__ qb,
             const float* __restrict__ kw, const float* __restrict__ kb,
             const float* __restrict__ vw, const float* __restrict__ vb)
{
    extern __shared__ __align__(16) char sm[];
    const uint32_t sb = smem_u32(sm);
    const int tid = threadIdx.x, wid = tid >> 5, lane = tid & 31;
    const int row0 = blockIdx.x * 128;
    const int b = row0 >> 10, n0 = row0 & 1023;
    if (n0 >= vls[b]) return;

    const float4* xg = (const float4*)(x + (size_t)row0 * CDIM);
    #pragma unroll
    for (int i = 0; i < 16; i++) {
        int idx = tid + (i << 8);
        int r = idx >> 5, c4 = idx & 31;
        float4 v = xg[r * 32 + c4];
        uint32_t h0 = cvt2h(v.x, v.y), h1 = cvt2h(v.z, v.w);
        uint32_t l0 = cvt2h(v.x - lo_hf(h0), v.y - hi_hf(h0));
        uint32_t l1 = cvt2h(v.z - lo_hf(h1), v.w - hi_hf(h1));
        uint32_t ad = (uint32_t)r * TS + (uint32_t)c4 * 8;
        *(uint2*)(sm + X_H + ad) = make_uint2(h0, h1);
        *(uint2*)(sm + X_L + ad) = make_uint2(l0, l1);
    }

    const uint32_t qrow = (uint32_t)(wid * 16 + (lane & 15)) * TS + ((lane >> 4) & 1) * 16;
    const uint32_t brow = (uint32_t)(lane & 7) * TS + ((lane >> 3) & 1) * 16;
    const int r0l = wid * 16 + (lane >> 2);

    for (int w = 0; w < 3; w++) {
        const float* W  = (w == 0) ? qw : (w == 1) ? kw : vw;
        const float* Bs = (w == 0) ? qb : (w == 1) ? kb : vb;
        __syncthreads();
        const float4* wg = (const float4*)W;
        #pragma unroll
        for (int i = 0; i < 16; i++) {
            int idx = tid + (i << 8);
            int r = idx >> 5, c4 = idx & 31;
            float4 v = wg[r * 32 + c4];
            uint32_t h0 = cvt2h(v.x, v.y), h1 = cvt2h(v.z, v.w);
            uint32_t l0 = cvt2h(v.x - lo_hf(h0), v.y - hi_hf(h0));
            uint32_t l1 = cvt2h(v.z - lo_hf(h1), v.w - hi_hf(h1));
            uint32_t ad = (uint32_t)r * TS + (uint32_t)c4 * 8;
            *(uint2*)(sm + W_H + ad) = make_uint2(h0, h1);
            *(uint2*)(sm + W_L + ad) = make_uint2(l0, l1);
        }
        __syncthreads();

        const uint32_t Ah = sb + ((w < 2) ? X_H : W_H), Al = sb + ((w < 2) ? X_L : W_L);
        const uint32_t Bh = sb + ((w < 2) ? W_H : X_H), Bl = sb + ((w < 2) ? W_L : X_L);

        float acc[16][4];
        #pragma unroll
        for (int n = 0; n < 16; n++)
            #pragma unroll
            for (int q = 0; q < 4; q++) acc[n][q] = 0.f;

        #pragma unroll
        for (int ks = 0; ks < 8; ks++) {
            uint32_t ah[4], al[4];
            ldmx4(Ah + qrow + ks * 32, ah);
            ldmx4(Al + qrow + ks * 32, al);
            #pragma unroll
            for (int n = 0; n < 16; n++) {
                uint32_t bh[2], bl[2];
                uint32_t off = brow + (uint32_t)n * (8 * TS) + ks * 32;
                asm volatile("ldmatrix.sync.aligned.m8n8.x2.shared.b16 {%0,%1}, [%2];"
                             : "=r"(bh[0]), "=r"(bh[1]) : "r"(Bh + off));
                asm volatile("ldmatrix.sync.aligned.m8n8.x2.shared.b16 {%0,%1}, [%2];"
                             : "=r"(bl[0]), "=r"(bl[1]) : "r"(Bl + off));
                mmah(acc[n], ah, bh);
                mmah(acc[n], al, bh);
                mmah(acc[n], ah, bl);
            }
        }

        if (w < 2) {
            unsigned short* Oh = (w == 0) ? g_Qh : g_Kh;
            unsigned short* Ol = (w == 0) ? g_Ql : g_Kl;
            const float sf = (w == 0) ? LOG2E : 1.0f;   // Q pre-scaled for exp2 softmax
            size_t rA = (size_t)(row0 + r0l) * CDIM;
            size_t rB = (size_t)(row0 + r0l + 8) * CDIM;
            #pragma unroll
            for (int n = 0; n < 16; n++) {
                int c = n * 8 + (lane & 3) * 2;
                float b0 = __ldg(Bs + c), b1 = __ldg(Bs + c + 1);
                float v00 = (acc[n][0] + b0) * sf, v01 = (acc[n][1] + b1) * sf;
                float v10 = (acc[n][2] + b0) * sf, v11 = (acc[n][3] + b1) * sf;
                uint32_t hA = cvt2h(v00, v01), hB = cvt2h(v10, v11);
                *(uint32_t*)(Oh + rA + c) = hA;
                *(uint32_t*)(Oh + rB + c) = hB;
                *(uint32_t*)(Ol + rA + c) = cvt2h(v00 - lo_hf(hA), v01 - hi_hf(hA));
                *(uint32_t*)(Ol + rB + c) = cvt2h(v10 - lo_hf(hB), v11 - hi_hf(hB));
            }
        } else {
            float bc0 = __ldg(Bs + r0l), bc1 = __ldg(Bs + r0l + 8);
            size_t rA = (size_t)b * CDIM * SEQ + (size_t)r0l * SEQ + n0;
            size_t rB = rA + (size_t)8 * SEQ;
            #pragma unroll
            for (int n = 0; n < 16; n++) {
                int c = n * 8 + (lane & 3) * 2;
                *(uint32_t*)(g_Vt + rA + c) = cvt2h(acc[n][0] + bc0, acc[n][1] + bc0);
                *(uint32_t*)(g_Vt + rB + c) = cvt2h(acc[n][2] + bc1, acc[n][3] + bc1);
            }
        }
    }
}

// ============================================================================
// Kernel 2: fp16 flash attention. 128-key double-buffered stages;
// softmax+PV at 64-key granularity (32 live sacc regs); exp2 softmax.
// ============================================================================
__global__ __launch_bounds__(256)
void attn_mma(const int* __restrict__ vls, float* __restrict__ out)
{
    extern __shared__ __align__(16) char sm[];
    const uint32_t sb = smem_u32(sm);
    const int tid = threadIdx.x, wid = tid >> 5, lane = tid & 31;
    const int b = blockIdx.y;
    const int row0 = (gridDim.x - 1 - blockIdx.x) * 128;   // heavy tiles first
    const int vl = vls[b];
    float* og = out + ((size_t)b * SEQ + row0) * CDIM;

    if (row0 >= vl) {
        float4 z = make_float4(0.f, 0.f, 0.f, 0.f);
        float4* o4 = (float4*)og;
        for (int i = tid; i < 128 * 32; i += 256) o4[i] = z;
        return;
    }

    const uint32_t qrow = (uint32_t)(wid * 16 + (lane & 15)) * TS + ((lane >> 4) & 1) * 16;
    const uint32_t brw  = (uint32_t)((lane & 7) + ((lane >> 4) << 3)) * TS + ((lane >> 3) & 1) * 16;
    const int r0l = wid * 16 + (lane >> 2);
    const bool v0 = row0 + r0l < vl, v1 = row0 + r0l + 8 < vl;

    const size_t kbase = (size_t)b * SEQ * CDIM;
    const size_t vbase = (size_t)b * CDIM * SEQ;
    const int nst = (vl + 127) >> 7;
    const uint32_t buf0 = sb, buf1 = sb + SSZ;

    // prologue: Q -> buf1, stage0 -> buf0
    loadT(buf1,         g_Qh + kbase + (size_t)row0 * CDIM, CDIM, tid);
    loadT(buf1 + 34816, g_Ql + kbase + (size_t)row0 * CDIM, CDIM, tid);
    stage_load(buf0, kbase, vbase, 0, tid);
    CP_COMMIT();
    CP_WAIT0();
    __syncthreads();

    uint32_t qh[8][4], ql[8][4];
    #pragma unroll
    for (int ks = 0; ks < 8; ks++) {
        ldmx4(buf1 +         qrow + ks * 32, qh[ks]);
        ldmx4(buf1 + 34816 + qrow + ks * 32, ql[ks]);
    }
    __syncthreads();            // all Q reads done before stage1 overwrites buf1

    float oacc[16][4];
    #pragma unroll
    for (int n = 0; n < 16; n++)
        #pragma unroll
        for (int q = 0; q < 4; q++) oacc[n][q] = 0.f;
    float lsum0 = 0.f, lsum1 = 0.f;
    float m0 = NEGM, m1 = NEGM;

    for (int t = 0; t < nst; t++) {
        if (t > 0) {
            CP_WAIT0();          // stage t resident
            __syncthreads();     // all warps past stage t-1 (buffer reuse safe)
        }
        if (t + 1 < nst) {
            stage_load((t & 1) ? buf0 : buf1, kbase, vbase, t + 1, tid);
            CP_COMMIT();
        }
        const uint32_t st = (t & 1) ? buf1 : buf0;
        const int rem = vl - t * 128;                  // keys remaining (>0 here)
        const int nh = (rem > 64) ? 2 : 1;             // halves with any valid key

        for (int h = 0; h < nh; h++) {
            const int cb = t * 128 + h * 64;
            const uint32_t hK = st + S_KH + (uint32_t)h * (64 * TS) + brw;
            const uint32_t hKl = st + S_KL + (uint32_t)h * (64 * TS) + brw;
            const uint32_t hV = st + S_V + (uint32_t)h * 128 + brw;

            // ---- S = Q K^T for 64 keys (3 split terms) ----
            float sacc[8][4];
            #pragma unroll
            for (int n = 0; n < 8; n++)
                #pragma unroll
                for (int q = 0; q < 4; q++) sacc[n][q] = 0.f;

            #pragma unroll
            for (int ks = 0; ks < 8; ks++) {
                #pragma unroll
                for (int g = 0; g < 2; g++) {
                    uint32_t b0h[4], b0l[4], b1h[4], b1l[4];
                    uint32_t off0 = (uint32_t)(2 * g)     * (16 * TS) + ks * 32;
                    uint32_t off1 = (uint32_t)(2 * g + 1) * (16 * TS) + ks * 32;
                    ldmx4(hK + off0, b0h);
                    ldmx4(hKl + off0, b0l);
                    ldmx4(hK + off1, b1h);
                    ldmx4(hKl + off1, b1l);
                    float* a0 = sacc[4 * g + 0];
                    float* a1 = sacc[4 * g + 1];
                    float* a2 = sacc[4 * g + 2];
                    float* a3 = sacc[4 * g + 3];
                    mmah(a0, qh[ks], b0h);  mmah(a1, qh[ks], b0h + 2);
                    mmah(a2, qh[ks], b1h);  mmah(a3, qh[ks], b1h + 2);
                    mmah(a0, ql[ks], b0h);  mmah(a1, ql[ks], b0h + 2);
                    mmah(a2, ql[ks], b1h);  mmah(a3, ql[ks], b1h + 2);
                    mmah(a0, qh[ks], b0l);  mmah(a1, qh[ks], b0l + 2);
                    mmah(a2, qh[ks], b1l);  mmah(a3, qh[ks], b1l + 2);
                }
            }

            // ---- mask BEFORE max (masked cols carry real scores) ----
            #pragma unroll
            for (int n = 0; n < 8; n++) {
                int c0 = cb + n * 8 + (lane & 3) * 2;
                if (c0 >= vl)     { sacc[n][0] = NEGM; sacc[n][2] = NEGM; }
                if (c0 + 1 >= vl) { sacc[n][1] = NEGM; sacc[n][3] = NEGM; }
            }

            // ---- online max (log2 domain), vote-guarded rescale ----
            float tm0 = NEGM, tm1 = NEGM;
            #pragma unroll
            for (int n = 0; n < 8; n++) {
                tm0 = fmaxf(tm0, fmaxf(sacc[n][0], sacc[n][1]));
                tm1 = fmaxf(tm1, fmaxf(sacc[n][2], sacc[n][3]));
            }
            tm0 = fmaxf(tm0, __shfl_xor_sync(0xffffffffu, tm0, 1));
            tm0 = fmaxf(tm0, __shfl_xor_sync(0xffffffffu, tm0, 2));
            tm1 = fmaxf(tm1, __shfl_xor_sync(0xffffffffu, tm1, 1));
            tm1 = fmaxf(tm1, __shfl_xor_sync(0xffffffffu, tm1, 2));
            if (__any_sync(0xffffffffu, tm0 > m0 || tm1 > m1)) {
                float mn0 = fmaxf(m0, tm0), mn1 = fmaxf(m1, tm1);
                float sc0 = exp2f(m0 - mn0), sc1 = exp2f(m1 - mn1);
                m0 = mn0; m1 = mn1;
                lsum0 *= sc0; lsum1 *= sc1;
                #pragma unroll
                for (int n = 0; n < 16; n++) {
                    oacc[n][0] *= sc0; oacc[n][1] *= sc0;
                    oacc[n][2] *= sc1; oacc[n][3] *= sc1;
                }
            }

            // ---- p = exp2(s - m) (scores already in log2 units via scaled Q) ----
            #pragma unroll
            for (int n = 0; n < 8; n++) {
                float e0 = exp2f(sacc[n][0] - m0);
                float e1 = exp2f(sacc[n][1] - m0);
                float e2 = exp2f(sacc[n][2] - m1);
                float e3 = exp2f(sacc[n][3] - m1);
                lsum0 += e0 + e1;
                lsum1 += e2 + e3;
                sacc[n][0] = e0; sacc[n][1] = e1; sacc[n][2] = e2; sacc[n][3] = e3;
            }

            // ---- O += P V (single fp16 term), 64 keys ----
            #pragma unroll
            for (int ks = 0; ks < 4; ks++) {
                const float* t0 = sacc[2 * ks];
                const float* t1 = sacc[2 * ks + 1];
                uint32_t pf[4];
                pf[0] = cvt2h(t0[0], t0[1]);
                pf[1] = cvt2h(t0[2], t0[3]);
                pf[2] = cvt2h(t1[0], t1[1]);
                pf[3] = cvt2h(t1[2], t1[3]);
                #pragma unroll
                for (int g = 0; g < 4; g++) {
                    uint32_t b0[4], b1[4];
                    uint32_t off0 = (uint32_t)(2 * g)     * (16 * TS) + ks * 32;
                    uint32_t off1 = (uint32_t)(2 * g + 1) * (16 * TS) + ks * 32;
                    ldmx4(hV + off0, b0);
                    ldmx4(hV + off1, b1);
                    mmah(oacc[4 * g + 0], pf, b0);  mmah(oacc[4 * g + 1], pf, b0 + 2);
                    mmah(oacc[4 * g + 2], pf, b1);  mmah(oacc[4 * g + 3], pf, b1 + 2);
                }
            }
        }
    }

    // ---- epilogue ----
    lsum0 += __shfl_xor_sync(0xffffffffu, lsum0, 1);
    lsum0 += __shfl_xor_sync(0xffffffffu, lsum0, 2);
    lsum1 += __shfl_xor_sync(0xffffffffu, lsum1, 1);
    lsum1 += __shfl_xor_sync(0xffffffffu, lsum1, 2);
    float inv0 = v0 ? (1.f / lsum0) : 0.f;
    float inv1 = v1 ? (1.f / lsum1) : 0.f;

    #pragma unroll
    for (int n = 0; n < 16; n++) {
        int c = n * 8 + (lane & 3) * 2;
        float2* p0 = (float2*)(og + (size_t)r0l * CDIM + c);
        float2* p1 = (float2*)(og + (size_t)(r0l + 8) * CDIM + c);
        *p0 = make_float2(oacc[n][0] * inv0, oacc[n][1] * inv0);
        *p1 = make_float2(oacc[n][2] * inv1, oacc[n][3] * inv1);
    }
}

// ============================================================================
extern "C" void kernel_launch(void* const* d_in, const int* in_sizes, int n_in,
                              void* d_out, int out_size)
{
    const float* x  = (const float*)d_in[0];
    const int*   vl = (const int*)  d_in[1];
    const float* qw = (const float*)d_in[2];
    const float* qb = (const float*)d_in[3];
    const float* kw = (const float*)d_in[4];
    const float* kb = (const float*)d_in[5];
    const float* vw = (const float*)d_in[6];
    const float* vb = (const float*)d_in[7];
    float* out = (float*)d_out;

    cudaFuncSetAttribute(qkv_mma,  cudaFuncAttributeMaxDynamicSharedMemorySize, QKV_SMEM);
    cudaFuncSetAttribute(attn_mma, cudaFuncAttributeMaxDynamicSharedMemorySize, ATT_SMEM);

    qkv_mma<<<(BATCH * SEQ) / 128, 256, QKV_SMEM>>>(x, vl, qw, qb, kw, kb, vw, vb);
    dim3 grid(SEQ / 128, BATCH);
    attn_mma<<<grid, 256, ATT_SMEM>>>(vl, out);
}